// round 7
// baseline (speedup 1.0000x reference)
#include <cuda_runtime.h>
#include <cuda_bf16.h>
#include <cuda_fp16.h>
#include <math.h>
#include <stdint.h>

#define BB 4
#define SS 2048
#define DD 1024
#define DFFN 4096
#define MM (BB*SS)
#define QKVW 3072
#define L2E 1.44269504088896f

__device__ float g_tmp[(size_t)MM * DD];
__device__ float g_res[(size_t)MM * DD];
__device__ __nv_bfloat16 g_ah[(size_t)MM * DD], g_al[(size_t)MM * DD];
__device__ __nv_bfloat16 g_qh[(size_t)MM * DD], g_ql[(size_t)MM * DD];
__device__ __nv_bfloat16 g_kh[(size_t)MM * DD], g_kl[(size_t)MM * DD];
__device__ __half        g_vh[(size_t)MM * DD], g_vl[(size_t)MM * DD];
__device__ __nv_bfloat16 g_ch[(size_t)MM * DD], g_cl[(size_t)MM * DD];
__device__ __nv_bfloat16 g_fh[(size_t)MM * DFFN], g_fl[(size_t)MM * DFFN];
#define W_QKV 0u
#define W_O   (3u*1024*1024)
#define W_I   (4u*1024*1024)
#define W_O2  (8u*1024*1024)
__device__ __nv_bfloat16 g_wh[12u*1024*1024], g_wl[12u*1024*1024];
__device__ float g_b3[QKVW];

__device__ __forceinline__ float gelu_f(float x) {
    return 0.5f * x * (1.0f + erff(x * 0.70710678118654752f));
}
__device__ __forceinline__ uint32_t s2u(const void* p) {
    uint32_t a;
    asm("{ .reg .u64 t; cvta.to.shared.u64 t, %1; cvt.u32.u64 %0, t; }" : "=r"(a) : "l"(p));
    return a;
}
__device__ __forceinline__ uint32_t swz(uint32_t off) {
    return off ^ (((off >> 7) & 7u) << 4);
}
__device__ __forceinline__ void cpa(uint32_t dst, const void* src) {
    asm volatile("cp.async.cg.shared.global [%0], [%1], 16;" :: "r"(dst), "l"(src));
}
__device__ __forceinline__ void ldsm4(uint32_t* r, uint32_t addr) {
    asm volatile("ldmatrix.sync.aligned.m8n8.x4.shared.b16 {%0,%1,%2,%3}, [%4];"
        : "=r"(r[0]), "=r"(r[1]), "=r"(r[2]), "=r"(r[3]) : "r"(addr));
}
__device__ __forceinline__ void ldsm4t(uint32_t* r, uint32_t addr) {
    asm volatile("ldmatrix.sync.aligned.m8n8.x4.trans.shared.b16 {%0,%1,%2,%3}, [%4];"
        : "=r"(r[0]), "=r"(r[1]), "=r"(r[2]), "=r"(r[3]) : "r"(addr));
}
__device__ __forceinline__ void mma16816(float* d, const uint32_t* a, const uint32_t* b) {
    asm volatile("mma.sync.aligned.m16n8k16.row.col.f32.bf16.bf16.f32 "
        "{%0,%1,%2,%3}, {%4,%5,%6,%7}, {%8,%9}, {%0,%1,%2,%3};"
        : "+f"(d[0]), "+f"(d[1]), "+f"(d[2]), "+f"(d[3])
        : "r"(a[0]), "r"(a[1]), "r"(a[2]), "r"(a[3]), "r"(b[0]), "r"(b[1]));
}
__device__ __forceinline__ void mmaf16(float* d, const uint32_t* a, const uint32_t* b) {
    asm volatile("mma.sync.aligned.m16n8k16.row.col.f32.f16.f16.f32 "
        "{%0,%1,%2,%3}, {%4,%5,%6,%7}, {%8,%9}, {%0,%1,%2,%3};"
        : "+f"(d[0]), "+f"(d[1]), "+f"(d[2]), "+f"(d[3])
        : "r"(a[0]), "r"(a[1]), "r"(a[2]), "r"(a[3]), "r"(b[0]), "r"(b[1]));
}
// FFMA-pipe exp2: magic-round + deg-4 Taylor on [-0.5,0.5] + exponent splice.
// Valid for x in (-126, 1); callers clamp to [-80, 0].
__device__ __forceinline__ float fexp2(float x) {
    const float C = 12582912.0f;   // 1.5 * 2^23
    const float t = x + C;
    const int bits = __float_as_int(t);
    const float f = x - (t - C);   // in [-0.5, 0.5]
    float p = 9.6181291e-3f;
    p = fmaf(p, f, 5.5504109e-2f);
    p = fmaf(p, f, 2.4022651e-1f);
    p = fmaf(p, f, 6.9314718e-1f);
    p = fmaf(p, f, 1.0f);
    const uint32_t sb = (((uint32_t)bits + 127u) << 23);  // (n+127)<<23
    return p * __int_as_float((int)sb);
}
// pack exp2(even)->lo, exp2(odd)->hi
__device__ __forceinline__ uint32_t exp2_pack(float odd, float even) {
    const float e0 = fexp2(fmaxf(even, -80.0f));
    const float e1 = fexp2(fmaxf(odd,  -80.0f));
    uint32_t r;
    asm("cvt.rn.f16x2.f32 %0, %1, %2;" : "=r"(r) : "f"(e1), "f"(e0));
    return r;
}

// W [K,N] fp32 -> hi/lo [N,K] bf16
__global__ __launch_bounds__(256)
void wsplit_kernel(const float* __restrict__ W, int N, int K,
                   __nv_bfloat16* __restrict__ hi, __nv_bfloat16* __restrict__ lo) {
    __shared__ float t[32][33];
    const int tx = threadIdx.x, ty = threadIdx.y;
    const int n0 = blockIdx.x * 32, k0 = blockIdx.y * 32;
    for (int j = ty; j < 32; j += 8) t[j][tx] = W[(size_t)(k0 + j) * N + n0 + tx];
    __syncthreads();
    for (int j = ty; j < 32; j += 8) {
        const float w = t[tx][j];
        const size_t o = (size_t)(n0 + j) * K + k0 + tx;
        const __nv_bfloat16 h = __float2bfloat16_rn(w);
        hi[o] = h;
        lo[o] = __float2bfloat16_rn(w - __bfloat162float(h));
    }
}

__global__ __launch_bounds__(256)
void split_kernel(const float* __restrict__ in, __nv_bfloat16* __restrict__ hi,
                  __nv_bfloat16* __restrict__ lo, int n4) {
    for (int i = blockIdx.x * 256 + threadIdx.x; i < n4; i += gridDim.x * 256) {
        const float4 v = ((const float4*)in)[i];
        const __nv_bfloat16 h0 = __float2bfloat16_rn(v.x), h1 = __float2bfloat16_rn(v.y);
        const __nv_bfloat16 h2 = __float2bfloat16_rn(v.z), h3 = __float2bfloat16_rn(v.w);
        ((__nv_bfloat162*)hi)[2*i+0] = __halves2bfloat162(h0, h1);
        ((__nv_bfloat162*)hi)[2*i+1] = __halves2bfloat162(h2, h3);
        ((__nv_bfloat162*)lo)[2*i+0] = __halves2bfloat162(
            __float2bfloat16_rn(v.x - __bfloat162float(h0)),
            __float2bfloat16_rn(v.y - __bfloat162float(h1)));
        ((__nv_bfloat162*)lo)[2*i+1] = __halves2bfloat162(
            __float2bfloat16_rn(v.z - __bfloat162float(h2)),
            __float2bfloat16_rn(v.w - __bfloat162float(h3)));
    }
}

__global__ void pack3_kernel(const float* a, const float* b, const float* c, float* o) {
    const float* s = (blockIdx.x == 0) ? a : (blockIdx.x == 1) ? b : c;
    o[blockIdx.x * 1024 + threadIdx.x] = s[threadIdx.x];
}

// ---- mma.sync bf16 GEMM, CTA 128x128, BK=64, 3-stage cp.async, 3-term split --
#define STG_B 65536
#define T_AH 0
#define T_AL 16384
#define T_BH 32768
#define T_BL 49152
#define GSMEM (3*STG_B)

__device__ __forceinline__ void load_stage(uint32_t sbase,
    const __nv_bfloat16* __restrict__ Ah, const __nv_bfloat16* __restrict__ Al,
    const __nv_bfloat16* __restrict__ Bh, const __nv_bfloat16* __restrict__ Bl,
    int K, int m0, int n0, int kb) {
    for (int i = threadIdx.x; i < 1024; i += 256) {
        const int row = i >> 3, cc = (i & 7) << 3;
        const uint32_t so = swz((uint32_t)(row * 128 + cc * 2));
        const size_t ka = (size_t)(m0 + row) * K + kb + cc;
        const size_t kbx = (size_t)(n0 + row) * K + kb + cc;
        cpa(sbase + T_AH + so, Ah + ka);
        cpa(sbase + T_AL + so, Al + ka);
        cpa(sbase + T_BH + so, Bh + kbx);
        cpa(sbase + T_BL + so, Bl + kbx);
    }
}

// mode 0: Cf fp32. mode 1: Ch/Cl bf16 split (+act). mode 2: qkv split out.
__global__ __launch_bounds__(256, 1)
void gemm_tc(const __nv_bfloat16* __restrict__ Ah, const __nv_bfloat16* __restrict__ Al,
             const __nv_bfloat16* __restrict__ Bh, const __nv_bfloat16* __restrict__ Bl,
             const float* __restrict__ bias, float* __restrict__ Cf,
             __nv_bfloat16* __restrict__ Ch, __nv_bfloat16* __restrict__ Cl,
             __nv_bfloat16* __restrict__ KH2, __nv_bfloat16* __restrict__ KL2,
             __half* __restrict__ VH2, __half* __restrict__ VL2,
             int N, int K, int act, int mode) {
    extern __shared__ char smv[];
    const uint32_t sb = s2u(smv);
    const int tid = threadIdx.x, lane = tid & 31, wid = tid >> 5;
    const int wm = wid & 3, wn = wid >> 2;
    const int m0 = blockIdx.y << 7, n0 = blockIdx.x << 7;
    const int nc = K >> 6;

    float acc[2][8][4];
#pragma unroll
    for (int i = 0; i < 2; i++)
#pragma unroll
        for (int j = 0; j < 8; j++)
#pragma unroll
            for (int q = 0; q < 4; q++) acc[i][j][q] = 0.0f;

    load_stage(sb, Ah, Al, Bh, Bl, K, m0, n0, 0);
    asm volatile("cp.async.commit_group;" ::: "memory");
    load_stage(sb + STG_B, Ah, Al, Bh, Bl, K, m0, n0, 64);
    asm volatile("cp.async.commit_group;" ::: "memory");

    const int a_r = (lane & 15);
    const int a_c = (lane >> 4) << 3;
    const int b_r = (lane & 7) + ((lane >> 4) << 3);
    const int b_c = ((lane >> 3) & 1) << 3;

    for (int c = 0; c < nc; c++) {
        if (c + 2 < nc)
            load_stage(sb + (uint32_t)((c + 2) % 3) * STG_B, Ah, Al, Bh, Bl,
                       K, m0, n0, (c + 2) << 6);
        asm volatile("cp.async.commit_group;" ::: "memory");
        asm volatile("cp.async.wait_group 2;" ::: "memory");
        __syncthreads();

        const uint32_t st = sb + (uint32_t)(c % 3) * STG_B;
#pragma unroll
        for (int ks = 0; ks < 4; ks++) {
            uint32_t afh[2][4], afl[2][4], bfh[8][2], bfl[8][2];
#pragma unroll
            for (int mt = 0; mt < 2; mt++) {
                const uint32_t off = swz((uint32_t)((wm*32 + mt*16 + a_r)*128 + (ks*16 + a_c)*2));
                ldsm4(afh[mt], st + T_AH + off);
                ldsm4(afl[mt], st + T_AL + off);
            }
#pragma unroll
            for (int p = 0; p < 4; p++) {
                const uint32_t off = swz((uint32_t)((wn*64 + p*16 + b_r)*128 + (ks*16 + b_c)*2));
                uint32_t t4[4];
                ldsm4(t4, st + T_BH + off);
                bfh[2*p][0]=t4[0]; bfh[2*p][1]=t4[1]; bfh[2*p+1][0]=t4[2]; bfh[2*p+1][1]=t4[3];
                ldsm4(t4, st + T_BL + off);
                bfl[2*p][0]=t4[0]; bfl[2*p][1]=t4[1]; bfl[2*p+1][0]=t4[2]; bfl[2*p+1][1]=t4[3];
            }
#pragma unroll
            for (int mt = 0; mt < 2; mt++)
#pragma unroll
                for (int nt = 0; nt < 8; nt++) {
                    mma16816(acc[mt][nt], afh[mt], bfh[nt]);
                    mma16816(acc[mt][nt], afh[mt], bfl[nt]);
                    mma16816(acc[mt][nt], afl[mt], bfh[nt]);
                }
        }
        __syncthreads();
    }

    const int rbase = m0 + wm * 32 + (lane >> 2);
    const int cbase = n0 + wn * 64 + ((lane & 3) << 1);
    const int region = n0 >> 10;
#pragma unroll
    for (int mt = 0; mt < 2; mt++) {
#pragma unroll
        for (int nt = 0; nt < 8; nt++) {
            const int col = cbase + nt * 8;
            const float2 bv = *(const float2*)&bias[col];
            float v0 = acc[mt][nt][0] + bv.x, v1 = acc[mt][nt][1] + bv.y;
            float v2 = acc[mt][nt][2] + bv.x, v3 = acc[mt][nt][3] + bv.y;
            if (act) { v0 = gelu_f(v0); v1 = gelu_f(v1); v2 = gelu_f(v2); v3 = gelu_f(v3); }
            const size_t r0 = (size_t)(rbase + mt * 16);
            const size_t r1 = r0 + 8;
            if (mode == 0) {
                *(float2*)&Cf[r0 * N + col] = make_float2(v0, v1);
                *(float2*)&Cf[r1 * N + col] = make_float2(v2, v3);
            } else if (mode == 1) {
                const __nv_bfloat16 h0 = __float2bfloat16_rn(v0), h1 = __float2bfloat16_rn(v1);
                const __nv_bfloat16 h2 = __float2bfloat16_rn(v2), h3 = __float2bfloat16_rn(v3);
                *(__nv_bfloat162*)&Ch[r0 * N + col] = __halves2bfloat162(h0, h1);
                *(__nv_bfloat162*)&Ch[r1 * N + col] = __halves2bfloat162(h2, h3);
                *(__nv_bfloat162*)&Cl[r0 * N + col] = __halves2bfloat162(
                    __float2bfloat16_rn(v0 - __bfloat162float(h0)),
                    __float2bfloat16_rn(v1 - __bfloat162float(h1)));
                *(__nv_bfloat162*)&Cl[r1 * N + col] = __halves2bfloat162(
                    __float2bfloat16_rn(v2 - __bfloat162float(h2)),
                    __float2bfloat16_rn(v3 - __bfloat162float(h3)));
            } else {
                const size_t cl_ = (size_t)(col - (region << 10));
                if (region < 2) {
                    __nv_bfloat16* H = region ? KH2 : Ch;
                    __nv_bfloat16* L = region ? KL2 : Cl;
                    const __nv_bfloat16 h0 = __float2bfloat16_rn(v0), h1 = __float2bfloat16_rn(v1);
                    const __nv_bfloat16 h2 = __float2bfloat16_rn(v2), h3 = __float2bfloat16_rn(v3);
                    *(__nv_bfloat162*)&H[r0 * DD + cl_] = __halves2bfloat162(h0, h1);
                    *(__nv_bfloat162*)&H[r1 * DD + cl_] = __halves2bfloat162(h2, h3);
                    *(__nv_bfloat162*)&L[r0 * DD + cl_] = __halves2bfloat162(
                        __float2bfloat16_rn(v0 - __bfloat162float(h0)),
                        __float2bfloat16_rn(v1 - __bfloat162float(h1)));
                    *(__nv_bfloat162*)&L[r1 * DD + cl_] = __halves2bfloat162(
                        __float2bfloat16_rn(v2 - __bfloat162float(h2)),
                        __float2bfloat16_rn(v3 - __bfloat162float(h3)));
                } else {
                    const __half h0 = __float2half_rn(v0), h1 = __float2half_rn(v1);
                    const __half h2 = __float2half_rn(v2), h3 = __float2half_rn(v3);
                    *(__half2*)&VH2[r0 * DD + cl_] = __halves2half2(h0, h1);
                    *(__half2*)&VH2[r1 * DD + cl_] = __halves2half2(h2, h3);
                    *(__half2*)&VL2[r0 * DD + cl_] = __halves2half2(
                        __float2half_rn(v0 - __half2float(h0)),
                        __float2half_rn(v1 - __half2float(h1)));
                    *(__half2*)&VL2[r1 * DD + cl_] = __halves2half2(
                        __float2half_rn(v2 - __half2float(h2)),
                        __float2half_rn(v3 - __half2float(h3)));
                }
            }
        }
    }
}

// ---- tensor-core flash attention: 128 q-rows/CTA, poly exp2, split QK/V ----
#define AT_QH 0
#define AT_QL 16384
#define AT_ST 32768
#define AT_SSZ 33024
#define AT_SMEM (32768 + 3*33024)

__global__ __launch_bounds__(256, 1)
void attn_mma(const __nv_bfloat16* __restrict__ qh, const __nv_bfloat16* __restrict__ ql,
              const __nv_bfloat16* __restrict__ kh, const __nv_bfloat16* __restrict__ kl,
              const __half* __restrict__ vh, const __half* __restrict__ vl,
              const float* __restrict__ mask,
              __nv_bfloat16* __restrict__ ch, __nv_bfloat16* __restrict__ cl) {
    extern __shared__ char smv[];
    const uint32_t sb = s2u(smv);
    const int tid = threadIdx.x, lane = tid & 31, wid = tid >> 5;
    const int b = blockIdx.y >> 4, h = blockIdx.y & 15;
    const int q0 = blockIdx.x << 7;
    const size_t hoff = (size_t)h * 64;

    for (int i = tid; i < 2048; i += 256) {
        const int t = i >> 10, idx = i & 1023, row = idx >> 3, cc = idx & 7;
        const __nv_bfloat16* src = (t ? ql : qh) + (size_t)(b*SS + q0 + row)*DD + hoff + cc*8;
        cpa(sb + AT_QH + t*16384 + swz((uint32_t)(row*128 + cc*16)), src);
    }
    for (int sidx = 0; sidx < 2; sidx++) {
        const int kt = sidx << 6;
        const uint32_t base = sb + AT_ST + (uint32_t)sidx * AT_SSZ;
        for (int i = tid; i < 2048; i += 256) {
            const int t = i >> 9, idx = i & 511, row = idx >> 3, cc = idx & 7;
            const uint32_t dst = base + t*8192 + swz((uint32_t)(row*128 + cc*16));
            const size_t goff = (size_t)(b*SS + kt + row)*DD + hoff + cc*8;
            if (t == 0) cpa(dst, kh + goff);
            else if (t == 1) cpa(dst, kl + goff);
            else if (t == 2) cpa(dst, vh + goff);
            else cpa(dst, vl + goff);
        }
        if (tid < 16) cpa(base + 32768 + tid*16, mask + (size_t)b*SS + kt + tid*4);
        asm volatile("cp.async.commit_group;" ::: "memory");
    }

    uint32_t qfh[4][4], qfl[4][4];
    float o[8][4], lacc[4];
    float mL0 = -1e30f, mL1 = -1e30f;
#pragma unroll
    for (int nt = 0; nt < 8; nt++) { o[nt][0]=o[nt][1]=o[nt][2]=o[nt][3]=0.f; }
    lacc[0]=lacc[1]=lacc[2]=lacc[3]=0.f;
    const uint32_t ones2[2] = {0x3C003C00u, 0x3C003C00u};

    for (int c = 0; c < SS/64; c++) {
        if (c + 2 < SS/64) {
            const int kt = (c + 2) << 6;
            const uint32_t base = sb + AT_ST + (uint32_t)((c+2) % 3) * AT_SSZ;
            for (int i = tid; i < 2048; i += 256) {
                const int t = i >> 9, idx = i & 511, row = idx >> 3, cc = idx & 7;
                const uint32_t dst = base + t*8192 + swz((uint32_t)(row*128 + cc*16));
                const size_t goff = (size_t)(b*SS + kt + row)*DD + hoff + cc*8;
                if (t == 0) cpa(dst, kh + goff);
                else if (t == 1) cpa(dst, kl + goff);
                else if (t == 2) cpa(dst, vh + goff);
                else cpa(dst, vl + goff);
            }
            if (tid < 16) cpa(base + 32768 + tid*16, mask + (size_t)b*SS + kt + tid*4);
        }
        asm volatile("cp.async.commit_group;" ::: "memory");
        asm volatile("cp.async.wait_group 2;" ::: "memory");
        __syncthreads();

        if (c == 0) {
#pragma unroll
            for (int ks = 0; ks < 4; ks++) {
                const int row = wid*16 + (lane & 15);
                const int colb = (ks*16 + ((lane >> 4) << 3)) * 2;
                ldsm4(qfh[ks], sb + AT_QH + swz((uint32_t)(row*128 + colb)));
                ldsm4(qfl[ks], sb + AT_QL + swz((uint32_t)(row*128 + colb)));
            }
        }

        const uint32_t soff = AT_ST + (uint32_t)(c % 3) * AT_SSZ;
        const uint32_t st = sb + soff;
        float S[8][4];
#pragma unroll
        for (int nt = 0; nt < 8; nt++) { S[nt][0]=S[nt][1]=S[nt][2]=S[nt][3]=0.f; }
#pragma unroll
        for (int ks = 0; ks < 4; ks++) {
            uint32_t kbh[8][2], kbl[8][2];
#pragma unroll
            for (int p = 0; p < 4; p++) {
                const int row = p*16 + (lane & 7) + ((lane >> 4) << 3);
                const int colb = (ks*16 + (((lane >> 3) & 1) << 3)) * 2;
                uint32_t t4[4];
                ldsm4(t4, st + swz((uint32_t)(row*128 + colb)));
                kbh[2*p][0]=t4[0]; kbh[2*p][1]=t4[1]; kbh[2*p+1][0]=t4[2]; kbh[2*p+1][1]=t4[3];
                ldsm4(t4, st + 8192 + swz((uint32_t)(row*128 + colb)));
                kbl[2*p][0]=t4[0]; kbl[2*p][1]=t4[1]; kbl[2*p+1][0]=t4[2]; kbl[2*p+1][1]=t4[3];
            }
#pragma unroll
            for (int nt = 0; nt < 8; nt++) {
                mma16816(S[nt], qfh[ks], kbh[nt]);
                mma16816(S[nt], qfh[ks], kbl[nt]);
                mma16816(S[nt], qfl[ks], kbh[nt]);
            }
        }
#pragma unroll
        for (int nt = 0; nt < 8; nt++) {
            const float2 mv = *(const float2*)(smv + soff + 32768 + (8*nt + 2*(lane&3))*4);
            S[nt][0] = fmaf(S[nt][0], 0.125f, mv.x);
            S[nt][1] = fmaf(S[nt][1], 0.125f, mv.y);
            S[nt][2] = fmaf(S[nt][2], 0.125f, mv.x);
            S[nt][3] = fmaf(S[nt][3], 0.125f, mv.y);
        }
        float mx0 = -1e30f, mx1 = -1e30f;
#pragma unroll
        for (int nt = 0; nt < 8; nt++) {
            mx0 = fmaxf(mx0, fmaxf(S[nt][0], S[nt][1]));
            mx1 = fmaxf(mx1, fmaxf(S[nt][2], S[nt][3]));
        }
        mx0 = fmaxf(mx0, __shfl_xor_sync(~0u, mx0, 1));
        mx0 = fmaxf(mx0, __shfl_xor_sync(~0u, mx0, 2));
        mx1 = fmaxf(mx1, __shfl_xor_sync(~0u, mx1, 1));
        mx1 = fmaxf(mx1, __shfl_xor_sync(~0u, mx1, 2));
        const float mLn0 = fmaxf(mL0, mx0 * L2E);
        const float mLn1 = fmaxf(mL1, mx1 * L2E);
        const float corr0 = fexp2(mL0 - mLn0);
        const float corr1 = fexp2(mL1 - mLn1);
        mL0 = mLn0; mL1 = mLn1;
        lacc[0] *= corr0; lacc[1] *= corr0; lacc[2] *= corr1; lacc[3] *= corr1;
#pragma unroll
        for (int nt = 0; nt < 8; nt++) {
            o[nt][0] *= corr0; o[nt][1] *= corr0; o[nt][2] *= corr1; o[nt][3] *= corr1;
        }
        uint32_t pf[4][4];
#pragma unroll
        for (int j = 0; j < 4; j++) {
            pf[j][0] = exp2_pack(fmaf(S[2*j][1],   L2E, -mL0), fmaf(S[2*j][0],   L2E, -mL0));
            pf[j][1] = exp2_pack(fmaf(S[2*j][3],   L2E, -mL1), fmaf(S[2*j][2],   L2E, -mL1));
            pf[j][2] = exp2_pack(fmaf(S[2*j+1][1], L2E, -mL0), fmaf(S[2*j+1][0], L2E, -mL0));
            pf[j][3] = exp2_pack(fmaf(S[2*j+1][3], L2E, -mL1), fmaf(S[2*j+1][2], L2E, -mL1));
        }
#pragma unroll
        for (int j = 0; j < 4; j++) mmaf16(lacc, pf[j], ones2);
#pragma unroll
        for (int j = 0; j < 4; j++) {
            const int krow = j*16 + (lane & 15);
#pragma unroll
            for (int pp = 0; pp < 4; pp++) {
                const int colb = (pp*16 + ((lane >> 4) << 3)) * 2;
                uint32_t vf[4];
                ldsm4t(vf, st + 16384 + swz((uint32_t)(krow*128 + colb)));
                mmaf16(o[2*pp],   pf[j], vf);
                mmaf16(o[2*pp+1], pf[j], vf + 2);
                ldsm4t(vf, st + 24576 + swz((uint32_t)(krow*128 + colb)));
                mmaf16(o[2*pp],   pf[j], vf);
                mmaf16(o[2*pp+1], pf[j], vf + 2);
            }
        }
        __syncthreads();
    }

    const float inv0 = 1.0f / lacc[0];
    const float inv1 = 1.0f / lacc[2];
    const size_t r0 = (size_t)(b*SS + q0 + wid*16 + (lane >> 2));
    const size_t r1 = r0 + 8;
#pragma unroll
    for (int nt = 0; nt < 8; nt++) {
        const size_t col = hoff + 8*nt + 2*(lane & 3);
        const float v0 = o[nt][0]*inv0, v1 = o[nt][1]*inv0;
        const float v2 = o[nt][2]*inv1, v3 = o[nt][3]*inv1;
        const __nv_bfloat16 h0 = __float2bfloat16_rn(v0), h1 = __float2bfloat16_rn(v1);
        const __nv_bfloat16 h2 = __float2bfloat16_rn(v2), h3 = __float2bfloat16_rn(v3);
        *(__nv_bfloat162*)&ch[r0*DD + col] = __halves2bfloat162(h0, h1);
        *(__nv_bfloat162*)&ch[r1*DD + col] = __halves2bfloat162(h2, h3);
        *(__nv_bfloat162*)&cl[r0*DD + col] = __halves2bfloat162(
            __float2bfloat16_rn(v0 - __bfloat162float(h0)),
            __float2bfloat16_rn(v1 - __bfloat162float(h1)));
        *(__nv_bfloat162*)&cl[r1*DD + col] = __halves2bfloat162(
            __float2bfloat16_rn(v2 - __bfloat162float(h2)),
            __float2bfloat16_rn(v3 - __bfloat162float(h3)));
    }
}

// ---- LayerNorm (optionally emits bf16 hi/lo of its output) ----
__device__ __forceinline__ float block_sum_256(float v) {
    __shared__ float red[8];
    const int lane = threadIdx.x & 31, w = threadIdx.x >> 5;
#pragma unroll
    for (int off = 16; off; off >>= 1) v += __shfl_xor_sync(0xffffffffu, v, off);
    __syncthreads();
    if (lane == 0) red[w] = v;
    __syncthreads();
    return red[0]+red[1]+red[2]+red[3]+red[4]+red[5]+red[6]+red[7];
}
__global__ __launch_bounds__(256)
void ln_kernel(const float* __restrict__ Y, const float* __restrict__ R,
               const float* __restrict__ g, const float* __restrict__ bta,
               float* __restrict__ out,
               __nv_bfloat16* __restrict__ hi, __nv_bfloat16* __restrict__ lo) {
    const int row = blockIdx.x, tid = threadIdx.x;
    float4 v = ((const float4*)(Y + (size_t)row * DD))[tid];
    const float4 r = ((const float4*)(R + (size_t)row * DD))[tid];
    v.x += r.x; v.y += r.y; v.z += r.z; v.w += r.w;
    const float mean = block_sum_256(v.x + v.y + v.z + v.w) * (1.0f/1024.0f);
    const float dx = v.x-mean, dy = v.y-mean, dz = v.z-mean, dw = v.w-mean;
    const float rstd = rsqrtf(block_sum_256(dx*dx + dy*dy + dz*dz + dw*dw) * (1.0f/1024.0f) + 1e-12f);
    const float4 gg = ((const float4*)g)[tid];
    const float4 bb = ((const float4*)bta)[tid];
    float4 o;
    o.x = dx*rstd*gg.x + bb.x; o.y = dy*rstd*gg.y + bb.y;
    o.z = dz*rstd*gg.z + bb.z; o.w = dw*rstd*gg.w + bb.w;
    ((float4*)(out + (size_t)row * DD))[tid] = o;
    if (hi) {
        const __nv_bfloat16 h0 = __float2bfloat16_rn(o.x), h1 = __float2bfloat16_rn(o.y);
        const __nv_bfloat16 h2 = __float2bfloat16_rn(o.z), h3 = __float2bfloat16_rn(o.w);
        ((__nv_bfloat162*)(hi + (size_t)row * DD))[2*tid]   = __halves2bfloat162(h0, h1);
        ((__nv_bfloat162*)(hi + (size_t)row * DD))[2*tid+1] = __halves2bfloat162(h2, h3);
        ((__nv_bfloat162*)(lo + (size_t)row * DD))[2*tid] = __halves2bfloat162(
            __float2bfloat16_rn(o.x - __bfloat162float(h0)),
            __float2bfloat16_rn(o.y - __bfloat162float(h1)));
        ((__nv_bfloat162*)(lo + (size_t)row * DD))[2*tid+1] = __halves2bfloat162(
            __float2bfloat16_rn(o.z - __bfloat162float(h2)),
            __float2bfloat16_rn(o.w - __bfloat162float(h3)));
    }
}

extern "C" void kernel_launch(void* const* d_in, const int* in_sizes, int n_in,
                              void* d_out, int out_size) {
    const float* x    = (const float*)d_in[0];
    const float* mask = (const float*)d_in[1];
    const float* Wq = (const float*)d_in[2];  const float* bq = (const float*)d_in[3];
    const float* Wk = (const float*)d_in[4];  const float* bk = (const float*)d_in[5];
    const float* Wv = (const float*)d_in[6];  const float* bv = (const float*)d_in[7];
    const float* Wo = (const float*)d_in[8];  const float* bo = (const float*)d_in[9];
    const float* ln1g = (const float*)d_in[10]; const float* ln1b = (const float*)d_in[11];
    const float* Wi = (const float*)d_in[12]; const float* bi = (const float*)d_in[13];
    const float* Wo2 = (const float*)d_in[14]; const float* bo2 = (const float*)d_in[15];
    const float* ln2g = (const float*)d_in[16]; const float* ln2b = (const float*)d_in[17];
    float* out = (float*)d_out;

    float *tmp, *res, *b3;
    __nv_bfloat16 *ah, *al, *qhp, *qlp, *khp, *klp, *chp, *clp, *fh, *fl, *wh, *wl;
    __half *vhp, *vlp;
    cudaGetSymbolAddress((void**)&tmp, g_tmp);
    cudaGetSymbolAddress((void**)&res, g_res);
    cudaGetSymbolAddress((void**)&b3, g_b3);
    cudaGetSymbolAddress((void**)&ah, g_ah);
    cudaGetSymbolAddress((void**)&al, g_al);
    cudaGetSymbolAddress((void**)&qhp, g_qh);
    cudaGetSymbolAddress((void**)&qlp, g_ql);
    cudaGetSymbolAddress((void**)&khp, g_kh);
    cudaGetSymbolAddress((void**)&klp, g_kl);
    cudaGetSymbolAddress((void**)&vhp, g_vh);
    cudaGetSymbolAddress((void**)&vlp, g_vl);
    cudaGetSymbolAddress((void**)&chp, g_ch);
    cudaGetSymbolAddress((void**)&clp, g_cl);
    cudaGetSymbolAddress((void**)&fh, g_fh);
    cudaGetSymbolAddress((void**)&fl, g_fl);
    cudaGetSymbolAddress((void**)&wh, g_wh);
    cudaGetSymbolAddress((void**)&wl, g_wl);

    cudaFuncSetAttribute(gemm_tc, cudaFuncAttributeMaxDynamicSharedMemorySize, GSMEM);
    cudaFuncSetAttribute(attn_mma, cudaFuncAttributeMaxDynamicSharedMemorySize, AT_SMEM);

    const dim3 tblk(32, 8);
    wsplit_kernel<<<dim3(32, 32),  tblk>>>(Wq,  DD,   DD,   wh + W_QKV,            wl + W_QKV);
    wsplit_kernel<<<dim3(32, 32),  tblk>>>(Wk,  DD,   DD,   wh + W_QKV + 1048576u, wl + W_QKV + 1048576u);
    wsplit_kernel<<<dim3(32, 32),  tblk>>>(Wv,  DD,   DD,   wh + W_QKV + 2097152u, wl + W_QKV + 2097152u);
    wsplit_kernel<<<dim3(32, 32),  tblk>>>(Wo,  DD,   DD,   wh + W_O,  wl + W_O);
    wsplit_kernel<<<dim3(128, 32), tblk>>>(Wi,  DFFN, DD,   wh + W_I,  wl + W_I);
    wsplit_kernel<<<dim3(32, 128), tblk>>>(Wo2, DD,   DFFN, wh + W_O2, wl + W_O2);
    pack3_kernel<<<3, 1024>>>(bq, bk, bv, b3);

    split_kernel<<<2048, 256>>>(x, ah, al, MM * DD / 4);
    gemm_tc<<<dim3(QKVW/128, MM/128), 256, GSMEM>>>(ah, al, wh + W_QKV, wl + W_QKV, b3,
        0, qhp, qlp, khp, klp, vhp, vlp, QKVW, DD, 0, 2);
    attn_mma<<<dim3(SS/128, BB*16), 256, AT_SMEM>>>(qhp, qlp, khp, klp, vhp, vlp, mask, chp, clp);
    gemm_tc<<<dim3(DD/128, MM/128), 256, GSMEM>>>(chp, clp, wh + W_O, wl + W_O, bo,
        tmp, 0, 0, 0, 0, 0, 0, DD, DD, 0, 0);
    ln_kernel<<<MM, 256>>>(tmp, x, ln1g, ln1b, res, ah, al);
    gemm_tc<<<dim3(DFFN/128, MM/128), 256, GSMEM>>>(ah, al, wh + W_I, wl + W_I, bi,
        0, fh, fl, 0, 0, 0, 0, DFFN, DD, 1, 1);
    gemm_tc<<<dim3(DD/128, MM/128), 256, GSMEM>>>(fh, fl, wh + W_O2, wl + W_O2, bo2,
        tmp, 0, 0, 0, 0, 0, 0, DD, DFFN, 0, 0);
    ln_kernel<<<MM, 256>>>(tmp, res, ln2g, ln2b, out, 0, 0);
}

// round 9
// speedup vs baseline: 2.0098x; 2.0098x over previous
#include <cuda_runtime.h>
#include <cuda_bf16.h>
#include <cuda_fp16.h>
#include <math.h>
#include <stdint.h>

#define BB 4
#define SS 2048
#define DD 1024
#define DFFN 4096
#define MM (BB*SS)
#define QKVW 3072
#define L2E 1.44269504088896f

__device__ float g_tmp[(size_t)MM * DD];
__device__ float g_res[(size_t)MM * DD];
__device__ __half g_x16[(size_t)MM * DD];
__device__ __half g_ln16[(size_t)MM * DD];
__device__ __half g_c16[(size_t)MM * DD];
__device__ __half g_f16[(size_t)MM * DFFN];
__device__ __nv_bfloat16 g_qh[(size_t)MM * DD], g_ql[(size_t)MM * DD];
__device__ __nv_bfloat16 g_kh[(size_t)MM * DD], g_kl[(size_t)MM * DD];
__device__ __half        g_vh[(size_t)MM * DD], g_vl[(size_t)MM * DD];
#define W_QKV 0u
#define W_O   (3u*1024*1024)
#define W_I   (4u*1024*1024)
#define W_O2  (8u*1024*1024)
__device__ __half g_wh[12u*1024*1024], g_wl[12u*1024*1024];
__device__ float g_b3[QKVW];

__device__ __forceinline__ float gelu_f(float x) {
    return 0.5f * x * (1.0f + erff(x * 0.70710678118654752f));
}
__device__ __forceinline__ uint32_t s2u(const void* p) {
    uint32_t a;
    asm("{ .reg .u64 t; cvta.to.shared.u64 t, %1; cvt.u32.u64 %0, t; }" : "=r"(a) : "l"(p));
    return a;
}
__device__ __forceinline__ uint32_t swz(uint32_t off) {
    return off ^ (((off >> 7) & 7u) << 4);
}
__device__ __forceinline__ void cpa(uint32_t dst, const void* src) {
    asm volatile("cp.async.cg.shared.global [%0], [%1], 16;" :: "r"(dst), "l"(src));
}
__device__ __forceinline__ void ldsm4(uint32_t* r, uint32_t addr) {
    asm volatile("ldmatrix.sync.aligned.m8n8.x4.shared.b16 {%0,%1,%2,%3}, [%4];"
        : "=r"(r[0]), "=r"(r[1]), "=r"(r[2]), "=r"(r[3]) : "r"(addr));
}
__device__ __forceinline__ void ldsm4t(uint32_t* r, uint32_t addr) {
    asm volatile("ldmatrix.sync.aligned.m8n8.x4.trans.shared.b16 {%0,%1,%2,%3}, [%4];"
        : "=r"(r[0]), "=r"(r[1]), "=r"(r[2]), "=r"(r[3]) : "r"(addr));
}
__device__ __forceinline__ void mma16816(float* d, const uint32_t* a, const uint32_t* b) {
    asm volatile("mma.sync.aligned.m16n8k16.row.col.f32.bf16.bf16.f32 "
        "{%0,%1,%2,%3}, {%4,%5,%6,%7}, {%8,%9}, {%0,%1,%2,%3};"
        : "+f"(d[0]), "+f"(d[1]), "+f"(d[2]), "+f"(d[3])
        : "r"(a[0]), "r"(a[1]), "r"(a[2]), "r"(a[3]), "r"(b[0]), "r"(b[1]));
}
__device__ __forceinline__ void mmaf16(float* d, const uint32_t* a, const uint32_t* b) {
    asm volatile("mma.sync.aligned.m16n8k16.row.col.f32.f16.f16.f32 "
        "{%0,%1,%2,%3}, {%4,%5,%6,%7}, {%8,%9}, {%0,%1,%2,%3};"
        : "+f"(d[0]), "+f"(d[1]), "+f"(d[2]), "+f"(d[3])
        : "r"(a[0]), "r"(a[1]), "r"(a[2]), "r"(a[3]), "r"(b[0]), "r"(b[1]));
}
// MUFU f16x2 exp2: pack (even->lo, odd->hi) then 2^x on both halves
__device__ __forceinline__ uint32_t exp2_pack(float odd, float even) {
    uint32_t p, r;
    asm("cvt.rn.f16x2.f32 %0, %1, %2;" : "=r"(p) : "f"(odd), "f"(even));
    asm("ex2.approx.f16x2 %0, %1;" : "=r"(r) : "r"(p));
    return r;
}

// W [K,N] fp32 -> hi/lo [N,K] fp16
__global__ __launch_bounds__(256)
void wsplit_kernel(const float* __restrict__ W, int N, int K,
                   __half* __restrict__ hi, __half* __restrict__ lo) {
    __shared__ float t[32][33];
    const int tx = threadIdx.x, ty = threadIdx.y;
    const int n0 = blockIdx.x * 32, k0 = blockIdx.y * 32;
    for (int j = ty; j < 32; j += 8) t[j][tx] = W[(size_t)(k0 + j) * N + n0 + tx];
    __syncthreads();
    for (int j = ty; j < 32; j += 8) {
        const float w = t[tx][j];
        const size_t o = (size_t)(n0 + j) * K + k0 + tx;
        const __half h = __float2half_rn(w);
        hi[o] = h;
        lo[o] = __float2half_rn(w - __half2float(h));
    }
}

// fp32 -> fp16 single
__global__ __launch_bounds__(256)
void split16_kernel(const float* __restrict__ in, __half* __restrict__ o16, int n4) {
    for (int i = blockIdx.x * 256 + threadIdx.x; i < n4; i += gridDim.x * 256) {
        const float4 v = ((const float4*)in)[i];
        ((__half2*)o16)[2*i+0] = __halves2half2(__float2half_rn(v.x), __float2half_rn(v.y));
        ((__half2*)o16)[2*i+1] = __halves2half2(__float2half_rn(v.z), __float2half_rn(v.w));
    }
}

__global__ void pack3_kernel(const float* a, const float* b, const float* c, float* o) {
    const float* s = (blockIdx.x == 0) ? a : (blockIdx.x == 1) ? b : c;
    o[blockIdx.x * 1024 + threadIdx.x] = s[threadIdx.x];
}

// ---- fp16 2-term GEMM: C[M,N] = A16[M,K] @ (Bh+Bl)[N,K]^T + bias ----
// CTA 128x128, BK=64, 3-stage cp.async.
#define STG_B 49152
#define T_A  0
#define T_BH 16384
#define T_BL 32768
#define GSMEM (3*STG_B)

__device__ __forceinline__ void load_stage(uint32_t sbase,
    const __half* __restrict__ A, const __half* __restrict__ Bh,
    const __half* __restrict__ Bl, int K, int m0, int n0, int kb) {
    for (int i = threadIdx.x; i < 1024; i += 256) {
        const int row = i >> 3, cc = (i & 7) << 3;
        const uint32_t so = swz((uint32_t)(row * 128 + cc * 2));
        const size_t ka = (size_t)(m0 + row) * K + kb + cc;
        const size_t kbx = (size_t)(n0 + row) * K + kb + cc;
        cpa(sbase + T_A + so, A + ka);
        cpa(sbase + T_BH + so, Bh + kbx);
        cpa(sbase + T_BL + so, Bl + kbx);
    }
}

// mode 0: Cf fp32. mode 1: C16 fp16 (+act). mode 2: qkv split out.
__global__ __launch_bounds__(256, 1)
void gemm_tc(const __half* __restrict__ A, const __half* __restrict__ Bh,
             const __half* __restrict__ Bl,
             const float* __restrict__ bias, float* __restrict__ Cf,
             __half* __restrict__ C16,
             __nv_bfloat16* __restrict__ QH, __nv_bfloat16* __restrict__ QL,
             __nv_bfloat16* __restrict__ KH, __nv_bfloat16* __restrict__ KL,
             __half* __restrict__ VH, __half* __restrict__ VL,
             int N, int K, int act, int mode) {
    extern __shared__ char smv[];
    const uint32_t sb = s2u(smv);
    const int tid = threadIdx.x, lane = tid & 31, wid = tid >> 5;
    const int wm = wid & 3, wn = wid >> 2;
    const int m0 = blockIdx.y << 7, n0 = blockIdx.x << 7;
    const int nc = K >> 6;

    float acc[2][8][4];
#pragma unroll
    for (int i = 0; i < 2; i++)
#pragma unroll
        for (int j = 0; j < 8; j++)
#pragma unroll
            for (int q = 0; q < 4; q++) acc[i][j][q] = 0.0f;

    load_stage(sb, A, Bh, Bl, K, m0, n0, 0);
    asm volatile("cp.async.commit_group;" ::: "memory");
    load_stage(sb + STG_B, A, Bh, Bl, K, m0, n0, 64);
    asm volatile("cp.async.commit_group;" ::: "memory");

    const int a_r = (lane & 15);
    const int a_c = (lane >> 4) << 3;
    const int b_r = (lane & 7) + ((lane >> 4) << 3);
    const int b_c = ((lane >> 3) & 1) << 3;

    for (int c = 0; c < nc; c++) {
        if (c + 2 < nc)
            load_stage(sb + (uint32_t)((c + 2) % 3) * STG_B, A, Bh, Bl,
                       K, m0, n0, (c + 2) << 6);
        asm volatile("cp.async.commit_group;" ::: "memory");
        asm volatile("cp.async.wait_group 2;" ::: "memory");
        __syncthreads();

        const uint32_t st = sb + (uint32_t)(c % 3) * STG_B;
#pragma unroll
        for (int ks = 0; ks < 4; ks++) {
            uint32_t af[2][4], bfh[8][2], bfl[8][2];
#pragma unroll
            for (int mt = 0; mt < 2; mt++) {
                const uint32_t off = swz((uint32_t)((wm*32 + mt*16 + a_r)*128 + (ks*16 + a_c)*2));
                ldsm4(af[mt], st + T_A + off);
            }
#pragma unroll
            for (int p = 0; p < 4; p++) {
                const uint32_t off = swz((uint32_t)((wn*64 + p*16 + b_r)*128 + (ks*16 + b_c)*2));
                uint32_t t4[4];
                ldsm4(t4, st + T_BH + off);
                bfh[2*p][0]=t4[0]; bfh[2*p][1]=t4[1]; bfh[2*p+1][0]=t4[2]; bfh[2*p+1][1]=t4[3];
                ldsm4(t4, st + T_BL + off);
                bfl[2*p][0]=t4[0]; bfl[2*p][1]=t4[1]; bfl[2*p+1][0]=t4[2]; bfl[2*p+1][1]=t4[3];
            }
#pragma unroll
            for (int mt = 0; mt < 2; mt++)
#pragma unroll
                for (int nt = 0; nt < 8; nt++) {
                    mmaf16(acc[mt][nt], af[mt], bfh[nt]);
                    mmaf16(acc[mt][nt], af[mt], bfl[nt]);
                }
        }
        __syncthreads();
    }

    const int rbase = m0 + wm * 32 + (lane >> 2);
    const int cbase = n0 + wn * 64 + ((lane & 3) << 1);
    const int region = n0 >> 10;
#pragma unroll
    for (int mt = 0; mt < 2; mt++) {
#pragma unroll
        for (int nt = 0; nt < 8; nt++) {
            const int col = cbase + nt * 8;
            const float2 bv = *(const float2*)&bias[col];
            float v0 = acc[mt][nt][0] + bv.x, v1 = acc[mt][nt][1] + bv.y;
            float v2 = acc[mt][nt][2] + bv.x, v3 = acc[mt][nt][3] + bv.y;
            if (act) { v0 = gelu_f(v0); v1 = gelu_f(v1); v2 = gelu_f(v2); v3 = gelu_f(v3); }
            const size_t r0 = (size_t)(rbase + mt * 16);
            const size_t r1 = r0 + 8;
            if (mode == 0) {
                *(float2*)&Cf[r0 * N + col] = make_float2(v0, v1);
                *(float2*)&Cf[r1 * N + col] = make_float2(v2, v3);
            } else if (mode == 1) {
                *(__half2*)&C16[r0 * N + col] = __halves2half2(__float2half_rn(v0), __float2half_rn(v1));
                *(__half2*)&C16[r1 * N + col] = __halves2half2(__float2half_rn(v2), __float2half_rn(v3));
            } else {
                const size_t cl_ = (size_t)(col - (region << 10));
                if (region < 2) {
                    __nv_bfloat16* H = region ? KH : QH;
                    __nv_bfloat16* L = region ? KL : QL;
                    const __nv_bfloat16 h0 = __float2bfloat16_rn(v0), h1 = __float2bfloat16_rn(v1);
                    const __nv_bfloat16 h2 = __float2bfloat16_rn(v2), h3 = __float2bfloat16_rn(v3);
                    *(__nv_bfloat162*)&H[r0 * DD + cl_] = __halves2bfloat162(h0, h1);
                    *(__nv_bfloat162*)&H[r1 * DD + cl_] = __halves2bfloat162(h2, h3);
                    *(__nv_bfloat162*)&L[r0 * DD + cl_] = __halves2bfloat162(
                        __float2bfloat16_rn(v0 - __bfloat162float(h0)),
                        __float2bfloat16_rn(v1 - __bfloat162float(h1)));
                    *(__nv_bfloat162*)&L[r1 * DD + cl_] = __halves2bfloat162(
                        __float2bfloat16_rn(v2 - __bfloat162float(h2)),
                        __float2bfloat16_rn(v3 - __bfloat162float(h3)));
                } else {
                    const __half h0 = __float2half_rn(v0), h1 = __float2half_rn(v1);
                    const __half h2 = __float2half_rn(v2), h3 = __float2half_rn(v3);
                    *(__half2*)&VH[r0 * DD + cl_] = __halves2half2(h0, h1);
                    *(__half2*)&VH[r1 * DD + cl_] = __halves2half2(h2, h3);
                    *(__half2*)&VL[r0 * DD + cl_] = __halves2half2(
                        __float2half_rn(v0 - __half2float(h0)),
                        __float2half_rn(v1 - __half2float(h1)));
                    *(__half2*)&VL[r1 * DD + cl_] = __halves2half2(
                        __float2half_rn(v2 - __half2float(h2)),
                        __float2half_rn(v3 - __half2float(h3)));
                }
            }
        }
    }
}

// ---- tensor-core flash attention: 128 q-rows/CTA, MUFU f16x2 exp, split QK/V ----
#define AT_QH 0
#define AT_QL 16384
#define AT_ST 32768
#define AT_SSZ 33024
#define AT_SMEM (32768 + 3*33024)

__global__ __launch_bounds__(256, 1)
void attn_mma(const __nv_bfloat16* __restrict__ qh, const __nv_bfloat16* __restrict__ ql,
              const __nv_bfloat16* __restrict__ kh, const __nv_bfloat16* __restrict__ kl,
              const __half* __restrict__ vh, const __half* __restrict__ vl,
              const float* __restrict__ mask, __half* __restrict__ c16) {
    extern __shared__ char smv[];
    const uint32_t sb = s2u(smv);
    const int tid = threadIdx.x, lane = tid & 31, wid = tid >> 5;
    const int b = blockIdx.y >> 4, h = blockIdx.y & 15;
    const int q0 = blockIdx.x << 7;
    const size_t hoff = (size_t)h * 64;

    for (int i = tid; i < 2048; i += 256) {
        const int t = i >> 10, idx = i & 1023, row = idx >> 3, cc = idx & 7;
        const __nv_bfloat16* src = (t ? ql : qh) + (size_t)(b*SS + q0 + row)*DD + hoff + cc*8;
        cpa(sb + AT_QH + t*16384 + swz((uint32_t)(row*128 + cc*16)), src);
    }
    for (int sidx = 0; sidx < 2; sidx++) {
        const int kt = sidx << 6;
        const uint32_t base = sb + AT_ST + (uint32_t)sidx * AT_SSZ;
        for (int i = tid; i < 2048; i += 256) {
            const int t = i >> 9, idx = i & 511, row = idx >> 3, cc = idx & 7;
            const uint32_t dst = base + t*8192 + swz((uint32_t)(row*128 + cc*16));
            const size_t goff = (size_t)(b*SS + kt + row)*DD + hoff + cc*8;
            if (t == 0) cpa(dst, kh + goff);
            else if (t == 1) cpa(dst, kl + goff);
            else if (t == 2) cpa(dst, vh + goff);
            else cpa(dst, vl + goff);
        }
        if (tid < 16) cpa(base + 32768 + tid*16, mask + (size_t)b*SS + kt + tid*4);
        asm volatile("cp.async.commit_group;" ::: "memory");
    }

    uint32_t qfh[4][4], qfl[4][4];
    float o[8][4], lacc[4];
    float mL0 = -1e30f, mL1 = -1e30f;
#pragma unroll
    for (int nt = 0; nt < 8; nt++) { o[nt][0]=o[nt][1]=o[nt][2]=o[nt][3]=0.f; }
    lacc[0]=lacc[1]=lacc[2]=lacc[3]=0.f;
    const uint32_t ones2[2] = {0x3C003C00u, 0x3C003C00u};

    for (int c = 0; c < SS/64; c++) {
        if (c + 2 < SS/64) {
            const int kt = (c + 2) << 6;
            const uint32_t base = sb + AT_ST + (uint32_t)((c+2) % 3) * AT_SSZ;
            for (int i = tid; i < 2048; i += 256) {
                const int t = i >> 9, idx = i & 511, row = idx >> 3, cc = idx & 7;
                const uint32_t dst = base + t*8192 + swz((uint32_t)(row*128 + cc*16));
                const size_t goff = (size_t)(b*SS + kt + row)*DD + hoff + cc*8;
                if (t == 0) cpa(dst, kh + goff);
                else if (t == 1) cpa(dst, kl + goff);
                else if (t == 2) cpa(dst, vh + goff);
                else cpa(dst, vl + goff);
            }
            if (tid < 16) cpa(base + 32768 + tid*16, mask + (size_t)b*SS + kt + tid*4);
        }
        asm volatile("cp.async.commit_group;" ::: "memory");
        asm volatile("cp.async.wait_group 2;" ::: "memory");
        __syncthreads();

        if (c == 0) {
#pragma unroll
            for (int ks = 0; ks < 4; ks++) {
                const int row = wid*16 + (lane & 15);
                const int colb = (ks*16 + ((lane >> 4) << 3)) * 2;
                ldsm4(qfh[ks], sb + AT_QH + swz((uint32_t)(row*128 + colb)));
                ldsm4(qfl[ks], sb + AT_QL + swz((uint32_t)(row*128 + colb)));
            }
        }

        const uint32_t soff = AT_ST + (uint32_t)(c % 3) * AT_SSZ;
        const uint32_t st = sb + soff;
        float S[8][4];
#pragma unroll
        for (int nt = 0; nt < 8; nt++) { S[nt][0]=S[nt][1]=S[nt][2]=S[nt][3]=0.f; }
#pragma unroll
        for (int ks = 0; ks < 4; ks++) {
            uint32_t kbh[8][2], kbl[8][2];
#pragma unroll
            for (int p = 0; p < 4; p++) {
                const int row = p*16 + (lane & 7) + ((lane >> 4) << 3);
                const int colb = (ks*16 + (((lane >> 3) & 1) << 3)) * 2;
                uint32_t t4[4];
                ldsm4(t4, st + swz((uint32_t)(row*128 + colb)));
                kbh[2*p][0]=t4[0]; kbh[2*p][1]=t4[1]; kbh[2*p+1][0]=t4[2]; kbh[2*p+1][1]=t4[3];
                ldsm4(t4, st + 8192 + swz((uint32_t)(row*128 + colb)));
                kbl[2*p][0]=t4[0]; kbl[2*p][1]=t4[1]; kbl[2*p+1][0]=t4[2]; kbl[2*p+1][1]=t4[3];
            }
#pragma unroll
            for (int nt = 0; nt < 8; nt++) {
                mma16816(S[nt], qfh[ks], kbh[nt]);
                mma16816(S[nt], qfh[ks], kbl[nt]);
                mma16816(S[nt], qfl[ks], kbh[nt]);
            }
        }
#pragma unroll
        for (int nt = 0; nt < 8; nt++) {
            const float2 mv = *(const float2*)(smv + soff + 32768 + (8*nt + 2*(lane&3))*4);
            S[nt][0] = fmaf(S[nt][0], 0.125f, mv.x);
            S[nt][1] = fmaf(S[nt][1], 0.125f, mv.y);
            S[nt][2] = fmaf(S[nt][2], 0.125f, mv.x);
            S[nt][3] = fmaf(S[nt][3], 0.125f, mv.y);
        }
        float mx0 = -1e30f, mx1 = -1e30f;
#pragma unroll
        for (int nt = 0; nt < 8; nt++) {
            mx0 = fmaxf(mx0, fmaxf(S[nt][0], S[nt][1]));
            mx1 = fmaxf(mx1, fmaxf(S[nt][2], S[nt][3]));
        }
        mx0 = fmaxf(mx0, __shfl_xor_sync(~0u, mx0, 1));
        mx0 = fmaxf(mx0, __shfl_xor_sync(~0u, mx0, 2));
        mx1 = fmaxf(mx1, __shfl_xor_sync(~0u, mx1, 1));
        mx1 = fmaxf(mx1, __shfl_xor_sync(~0u, mx1, 2));
        const float mLn0 = fmaxf(mL0, mx0 * L2E);
        const float mLn1 = fmaxf(mL1, mx1 * L2E);
        const float corr0 = exp2f(mL0 - mLn0);
        const float corr1 = exp2f(mL1 - mLn1);
        mL0 = mLn0; mL1 = mLn1;
        lacc[0] *= corr0; lacc[1] *= corr0; lacc[2] *= corr1; lacc[3] *= corr1;
#pragma unroll
        for (int nt = 0; nt < 8; nt++) {
            o[nt][0] *= corr0; o[nt][1] *= corr0; o[nt][2] *= corr1; o[nt][3] *= corr1;
        }
        uint32_t pf[4][4];
#pragma unroll
        for (int j = 0; j < 4; j++) {
            pf[j][0] = exp2_pack(fmaf(S[2*j][1],   L2E, -mL0), fmaf(S[2*j][0],   L2E, -mL0));
            pf[j][1] = exp2_pack(fmaf(S[2*j][3],   L2E, -mL1), fmaf(S[2*j][2],   L2E, -mL1));
            pf[j][2] = exp2_pack(fmaf(S[2*j+1][1], L2E, -mL0), fmaf(S[2*j+1][0], L2E, -mL0));
            pf[j][3] = exp2_pack(fmaf(S[2*j+1][3], L2E, -mL1), fmaf(S[2*j+1][2], L2E, -mL1));
        }
#pragma unroll
        for (int j = 0; j < 4; j++) mmaf16(lacc, pf[j], ones2);
#pragma unroll
        for (int j = 0; j < 4; j++) {
            const int krow = j*16 + (lane & 15);
#pragma unroll
            for (int pp = 0; pp < 4; pp++) {
                const int colb = (pp*16 + ((lane >> 4) << 3)) * 2;
                uint32_t vf[4];
                ldsm4t(vf, st + 16384 + swz((uint32_t)(krow*128 + colb)));
                mmaf16(o[2*pp],   pf[j], vf);
                mmaf16(o[2*pp+1], pf[j], vf + 2);
                ldsm4t(vf, st + 24576 + swz((uint32_t)(krow*128 + colb)));
                mmaf16(o[2*pp],   pf[j], vf);
                mmaf16(o[2*pp+1], pf[j], vf + 2);
            }
        }
        __syncthreads();
    }

    const float inv0 = 1.0f / lacc[0];
    const float inv1 = 1.0f / lacc[2];
    const size_t r0 = (size_t)(b*SS + q0 + wid*16 + (lane >> 2));
    const size_t r1 = r0 + 8;
#pragma unroll
    for (int nt = 0; nt < 8; nt++) {
        const size_t col = hoff + 8*nt + 2*(lane & 3);
        *(__half2*)&c16[r0*DD + col] = __halves2half2(
            __float2half_rn(o[nt][0]*inv0), __float2half_rn(o[nt][1]*inv0));
        *(__half2*)&c16[r1*DD + col] = __halves2half2(
            __float2half_rn(o[nt][2]*inv1), __float2half_rn(o[nt][3]*inv1));
    }
}

// ---- LayerNorm (optionally emits fp16 of its output) ----
__device__ __forceinline__ float block_sum_256(float v) {
    __shared__ float red[8];
    const int lane = threadIdx.x & 31, w = threadIdx.x >> 5;
#pragma unroll
    for (int off = 16; off; off >>= 1) v += __shfl_xor_sync(0xffffffffu, v, off);
    __syncthreads();
    if (lane == 0) red[w] = v;
    __syncthreads();
    return red[0]+red[1]+red[2]+red[3]+red[4]+red[5]+red[6]+red[7];
}
__global__ __launch_bounds__(256)
void ln_kernel(const float* __restrict__ Y, const float* __restrict__ R,
               const float* __restrict__ g, const float* __restrict__ bta,
               float* __restrict__ out, __half* __restrict__ h16) {
    const int row = blockIdx.x, tid = threadIdx.x;
    float4 v = ((const float4*)(Y + (size_t)row * DD))[tid];
    const float4 r = ((const float4*)(R + (size_t)row * DD))[tid];
    v.x += r.x; v.y += r.y; v.z += r.z; v.w += r.w;
    const float mean = block_sum_256(v.x + v.y + v.z + v.w) * (1.0f/1024.0f);
    const float dx = v.x-mean, dy = v.y-mean, dz = v.z-mean, dw = v.w-mean;
    const float rstd = rsqrtf(block_sum_256(dx*dx + dy*dy + dz*dz + dw*dw) * (1.0f/1024.0f) + 1e-12f);
    const float4 gg = ((const float4*)g)[tid];
    const float4 bb = ((const float4*)bta)[tid];
    float4 o;
    o.x = dx*rstd*gg.x + bb.x; o.y = dy*rstd*gg.y + bb.y;
    o.z = dz*rstd*gg.z + bb.z; o.w = dw*rstd*gg.w + bb.w;
    ((float4*)(out + (size_t)row * DD))[tid] = o;
    if (h16) {
        ((__half2*)(h16 + (size_t)row * DD))[2*tid] =
            __halves2half2(__float2half_rn(o.x), __float2half_rn(o.y));
        ((__half2*)(h16 + (size_t)row * DD))[2*tid+1] =
            __halves2half2(__float2half_rn(o.z), __float2half_rn(o.w));
    }
}

extern "C" void kernel_launch(void* const* d_in, const int* in_sizes, int n_in,
                              void* d_out, int out_size) {
    const float* x    = (const float*)d_in[0];
    const float* mask = (const float*)d_in[1];
    const float* Wq = (const float*)d_in[2];  const float* bq = (const float*)d_in[3];
    const float* Wk = (const float*)d_in[4];  const float* bk = (const float*)d_in[5];
    const float* Wv = (const float*)d_in[6];  const float* bv = (const float*)d_in[7];
    const float* Wo = (const float*)d_in[8];  const float* bo = (const float*)d_in[9];
    const float* ln1g = (const float*)d_in[10]; const float* ln1b = (const float*)d_in[11];
    const float* Wi = (const float*)d_in[12]; const float* bi = (const float*)d_in[13];
    const float* Wo2 = (const float*)d_in[14]; const float* bo2 = (const float*)d_in[15];
    const float* ln2g = (const float*)d_in[16]; const float* ln2b = (const float*)d_in[17];
    float* out = (float*)d_out;

    float *tmp, *res, *b3;
    __half *x16, *ln16, *c16, *f16, *vhp, *vlp, *wh, *wl;
    __nv_bfloat16 *qhp, *qlp, *khp, *klp;
    cudaGetSymbolAddress((void**)&tmp, g_tmp);
    cudaGetSymbolAddress((void**)&res, g_res);
    cudaGetSymbolAddress((void**)&b3, g_b3);
    cudaGetSymbolAddress((void**)&x16, g_x16);
    cudaGetSymbolAddress((void**)&ln16, g_ln16);
    cudaGetSymbolAddress((void**)&c16, g_c16);
    cudaGetSymbolAddress((void**)&f16, g_f16);
    cudaGetSymbolAddress((void**)&qhp, g_qh);
    cudaGetSymbolAddress((void**)&qlp, g_ql);
    cudaGetSymbolAddress((void**)&khp, g_kh);
    cudaGetSymbolAddress((void**)&klp, g_kl);
    cudaGetSymbolAddress((void**)&vhp, g_vh);
    cudaGetSymbolAddress((void**)&vlp, g_vl);
    cudaGetSymbolAddress((void**)&wh, g_wh);
    cudaGetSymbolAddress((void**)&wl, g_wl);

    cudaFuncSetAttribute(gemm_tc, cudaFuncAttributeMaxDynamicSharedMemorySize, GSMEM);
    cudaFuncSetAttribute(attn_mma, cudaFuncAttributeMaxDynamicSharedMemorySize, AT_SMEM);

    const dim3 tblk(32, 8);
    wsplit_kernel<<<dim3(32, 32),  tblk>>>(Wq,  DD,   DD,   wh + W_QKV,            wl + W_QKV);
    wsplit_kernel<<<dim3(32, 32),  tblk>>>(Wk,  DD,   DD,   wh + W_QKV + 1048576u, wl + W_QKV + 1048576u);
    wsplit_kernel<<<dim3(32, 32),  tblk>>>(Wv,  DD,   DD,   wh + W_QKV + 2097152u, wl + W_QKV + 2097152u);
    wsplit_kernel<<<dim3(32, 32),  tblk>>>(Wo,  DD,   DD,   wh + W_O,  wl + W_O);
    wsplit_kernel<<<dim3(128, 32), tblk>>>(Wi,  DFFN, DD,   wh + W_I,  wl + W_I);
    wsplit_kernel<<<dim3(32, 128), tblk>>>(Wo2, DD,   DFFN, wh + W_O2, wl + W_O2);
    pack3_kernel<<<3, 1024>>>(bq, bk, bv, b3);

    split16_kernel<<<2048, 256>>>(x, x16, MM * DD / 4);
    gemm_tc<<<dim3(QKVW/128, MM/128), 256, GSMEM>>>(x16, wh + W_QKV, wl + W_QKV, b3,
        0, 0, qhp, qlp, khp, klp, vhp, vlp, QKVW, DD, 0, 2);
    attn_mma<<<dim3(SS/128, BB*16), 256, AT_SMEM>>>(qhp, qlp, khp, klp, vhp, vlp, mask, c16);
    gemm_tc<<<dim3(DD/128, MM/128), 256, GSMEM>>>(c16, wh + W_O, wl + W_O, bo,
        tmp, 0, 0, 0, 0, 0, 0, 0, DD, DD, 0, 0);
    ln_kernel<<<MM, 256>>>(tmp, x, ln1g, ln1b, res, ln16);
    gemm_tc<<<dim3(DFFN/128, MM/128), 256, GSMEM>>>(ln16, wh + W_I, wl + W_I, bi,
        0, f16, 0, 0, 0, 0, 0, 0, DFFN, DD, 1, 1);
    gemm_tc<<<dim3(DD/128, MM/128), 256, GSMEM>>>(f16, wh + W_O2, wl + W_O2, bo2,
        tmp, 0, 0, 0, 0, 0, 0, 0, DD, DFFN, 0, 0);
    ln_kernel<<<MM, 256>>>(tmp, res, ln2g, ln2b, out, 0);
}

// round 10
// speedup vs baseline: 3.0601x; 1.5226x over previous
#include <cuda_runtime.h>
#include <cuda_bf16.h>
#include <cuda_fp16.h>
#include <math.h>
#include <stdint.h>

#define BB 4
#define SS 2048
#define DD 1024
#define DFFN 4096
#define MM (BB*SS)
#define QKVW 3072
#define L2E 1.44269504088896f

__device__ float g_tmp[(size_t)MM * DD];
__device__ float g_res[(size_t)MM * DD];
__device__ __half g_x16[(size_t)MM * DD];
__device__ __half g_ln16[(size_t)MM * DD];
__device__ __half g_c16[(size_t)MM * DD];
__device__ __half g_f16[(size_t)MM * DFFN];
__device__ __half g_q16[(size_t)MM * DD];
__device__ __half g_k16[(size_t)MM * DD];
__device__ __half g_v16[(size_t)MM * DD];
#define W_QKV 0u
#define W_O   (3u*1024*1024)
#define W_I   (4u*1024*1024)
#define W_O2  (8u*1024*1024)
__device__ __half g_wh[12u*1024*1024];
__device__ float g_b3[QKVW];

__device__ __forceinline__ float gelu_f(float x) {
    return 0.5f * x * (1.0f + erff(x * 0.70710678118654752f));
}
__device__ __forceinline__ uint32_t s2u(const void* p) {
    uint32_t a;
    asm("{ .reg .u64 t; cvta.to.shared.u64 t, %1; cvt.u32.u64 %0, t; }" : "=r"(a) : "l"(p));
    return a;
}
__device__ __forceinline__ uint32_t swz(uint32_t off) {
    return off ^ (((off >> 7) & 7u) << 4);
}
__device__ __forceinline__ void cpa(uint32_t dst, const void* src) {
    asm volatile("cp.async.cg.shared.global [%0], [%1], 16;" :: "r"(dst), "l"(src));
}
__device__ __forceinline__ void ldsm4(uint32_t* r, uint32_t addr) {
    asm volatile("ldmatrix.sync.aligned.m8n8.x4.shared.b16 {%0,%1,%2,%3}, [%4];"
        : "=r"(r[0]), "=r"(r[1]), "=r"(r[2]), "=r"(r[3]) : "r"(addr));
}
__device__ __forceinline__ void ldsm4t(uint32_t* r, uint32_t addr) {
    asm volatile("ldmatrix.sync.aligned.m8n8.x4.trans.shared.b16 {%0,%1,%2,%3}, [%4];"
        : "=r"(r[0]), "=r"(r[1]), "=r"(r[2]), "=r"(r[3]) : "r"(addr));
}
__device__ __forceinline__ void mmaf16(float* d, const uint32_t* a, const uint32_t* b) {
    asm volatile("mma.sync.aligned.m16n8k16.row.col.f32.f16.f16.f32 "
        "{%0,%1,%2,%3}, {%4,%5,%6,%7}, {%8,%9}, {%0,%1,%2,%3};"
        : "+f"(d[0]), "+f"(d[1]), "+f"(d[2]), "+f"(d[3])
        : "r"(a[0]), "r"(a[1]), "r"(a[2]), "r"(a[3]), "r"(b[0]), "r"(b[1]));
}
// MUFU f16x2 exp2: pack (even->lo, odd->hi) then 2^x on both halves
__device__ __forceinline__ uint32_t exp2_pack(float odd, float even) {
    uint32_t p, r;
    asm("cvt.rn.f16x2.f32 %0, %1, %2;" : "=r"(p) : "f"(odd), "f"(even));
    asm("ex2.approx.f16x2 %0, %1;" : "=r"(r) : "r"(p));
    return r;
}

// W [K,N] fp32 -> [N,K] fp16
__global__ __launch_bounds__(256)
void wconv_kernel(const float* __restrict__ W, int N, int K, __half* __restrict__ hi) {
    __shared__ float t[32][33];
    const int tx = threadIdx.x, ty = threadIdx.y;
    const int n0 = blockIdx.x * 32, k0 = blockIdx.y * 32;
    for (int j = ty; j < 32; j += 8) t[j][tx] = W[(size_t)(k0 + j) * N + n0 + tx];
    __syncthreads();
    for (int j = ty; j < 32; j += 8)
        hi[(size_t)(n0 + j) * K + k0 + tx] = __float2half_rn(t[tx][j]);
}

// fp32 -> fp16
__global__ __launch_bounds__(256)
void split16_kernel(const float* __restrict__ in, __half* __restrict__ o16, int n4) {
    for (int i = blockIdx.x * 256 + threadIdx.x; i < n4; i += gridDim.x * 256) {
        const float4 v = ((const float4*)in)[i];
        ((__half2*)o16)[2*i+0] = __halves2half2(__float2half_rn(v.x), __float2half_rn(v.y));
        ((__half2*)o16)[2*i+1] = __halves2half2(__float2half_rn(v.z), __float2half_rn(v.w));
    }
}

__global__ void pack3_kernel(const float* a, const float* b, const float* c, float* o) {
    const float* s = (blockIdx.x == 0) ? a : (blockIdx.x == 1) ? b : c;
    o[blockIdx.x * 1024 + threadIdx.x] = s[threadIdx.x];
}

// ---- fp16 GEMM: C[M,N] = A16[M,K] @ B16[N,K]^T + bias ----
// CTA 128x128, BK=64, 3-stage cp.async, 1 mma per warp-tile pair.
#define STG_B 32768
#define T_A  0
#define T_B  16384
#define GSMEM (3*STG_B)

__device__ __forceinline__ void load_stage(uint32_t sbase,
    const __half* __restrict__ A, const __half* __restrict__ B,
    int K, int m0, int n0, int kb) {
    for (int i = threadIdx.x; i < 1024; i += 256) {
        const int row = i >> 3, cc = (i & 7) << 3;
        const uint32_t so = swz((uint32_t)(row * 128 + cc * 2));
        cpa(sbase + T_A + so, A + (size_t)(m0 + row) * K + kb + cc);
        cpa(sbase + T_B + so, B + (size_t)(n0 + row) * K + kb + cc);
    }
}

// mode 0: Cf fp32. mode 1: C16 fp16 (+act). mode 2: q/k/v fp16 out.
__global__ __launch_bounds__(256, 1)
void gemm_tc(const __half* __restrict__ A, const __half* __restrict__ B,
             const float* __restrict__ bias, float* __restrict__ Cf,
             __half* __restrict__ C16,
             __half* __restrict__ Q16, __half* __restrict__ K16, __half* __restrict__ V16,
             int N, int K, int act, int mode) {
    extern __shared__ char smv[];
    const uint32_t sb = s2u(smv);
    const int tid = threadIdx.x, lane = tid & 31, wid = tid >> 5;
    const int wm = wid & 3, wn = wid >> 2;
    const int m0 = blockIdx.y << 7, n0 = blockIdx.x << 7;
    const int nc = K >> 6;

    float acc[2][8][4];
#pragma unroll
    for (int i = 0; i < 2; i++)
#pragma unroll
        for (int j = 0; j < 8; j++)
#pragma unroll
            for (int q = 0; q < 4; q++) acc[i][j][q] = 0.0f;

    load_stage(sb, A, B, K, m0, n0, 0);
    asm volatile("cp.async.commit_group;" ::: "memory");
    load_stage(sb + STG_B, A, B, K, m0, n0, 64);
    asm volatile("cp.async.commit_group;" ::: "memory");

    const int a_r = (lane & 15);
    const int a_c = (lane >> 4) << 3;
    const int b_r = (lane & 7) + ((lane >> 4) << 3);
    const int b_c = ((lane >> 3) & 1) << 3;

    for (int c = 0; c < nc; c++) {
        if (c + 2 < nc)
            load_stage(sb + (uint32_t)((c + 2) % 3) * STG_B, A, B, K, m0, n0, (c + 2) << 6);
        asm volatile("cp.async.commit_group;" ::: "memory");
        asm volatile("cp.async.wait_group 2;" ::: "memory");
        __syncthreads();

        const uint32_t st = sb + (uint32_t)(c % 3) * STG_B;
#pragma unroll
        for (int ks = 0; ks < 4; ks++) {
            uint32_t af[2][4], bf[8][2];
#pragma unroll
            for (int mt = 0; mt < 2; mt++) {
                const uint32_t off = swz((uint32_t)((wm*32 + mt*16 + a_r)*128 + (ks*16 + a_c)*2));
                ldsm4(af[mt], st + T_A + off);
            }
#pragma unroll
            for (int p = 0; p < 4; p++) {
                const uint32_t off = swz((uint32_t)((wn*64 + p*16 + b_r)*128 + (ks*16 + b_c)*2));
                uint32_t t4[4];
                ldsm4(t4, st + T_B + off);
                bf[2*p][0]=t4[0]; bf[2*p][1]=t4[1]; bf[2*p+1][0]=t4[2]; bf[2*p+1][1]=t4[3];
            }
#pragma unroll
            for (int mt = 0; mt < 2; mt++)
#pragma unroll
                for (int nt = 0; nt < 8; nt++)
                    mmaf16(acc[mt][nt], af[mt], bf[nt]);
        }
        __syncthreads();
    }

    const int rbase = m0 + wm * 32 + (lane >> 2);
    const int cbase = n0 + wn * 64 + ((lane & 3) << 1);
    const int region = n0 >> 10;
#pragma unroll
    for (int mt = 0; mt < 2; mt++) {
#pragma unroll
        for (int nt = 0; nt < 8; nt++) {
            const int col = cbase + nt * 8;
            const float2 bv = *(const float2*)&bias[col];
            float v0 = acc[mt][nt][0] + bv.x, v1 = acc[mt][nt][1] + bv.y;
            float v2 = acc[mt][nt][2] + bv.x, v3 = acc[mt][nt][3] + bv.y;
            if (act) { v0 = gelu_f(v0); v1 = gelu_f(v1); v2 = gelu_f(v2); v3 = gelu_f(v3); }
            const size_t r0 = (size_t)(rbase + mt * 16);
            const size_t r1 = r0 + 8;
            if (mode == 0) {
                *(float2*)&Cf[r0 * N + col] = make_float2(v0, v1);
                *(float2*)&Cf[r1 * N + col] = make_float2(v2, v3);
            } else if (mode == 1) {
                *(__half2*)&C16[r0 * N + col] = __halves2half2(__float2half_rn(v0), __float2half_rn(v1));
                *(__half2*)&C16[r1 * N + col] = __halves2half2(__float2half_rn(v2), __float2half_rn(v3));
            } else {
                const size_t cl_ = (size_t)(col - (region << 10));
                __half* D = (region == 0) ? Q16 : (region == 1) ? K16 : V16;
                *(__half2*)&D[r0 * DD + cl_] = __halves2half2(__float2half_rn(v0), __float2half_rn(v1));
                *(__half2*)&D[r1 * DD + cl_] = __halves2half2(__float2half_rn(v2), __float2half_rn(v3));
            }
        }
    }
}

// ---- fp16 flash attention: 128 q-rows/CTA, MUFU f16x2 exp ----
#define AT_Q 0
#define AT_ST 16384
#define AT_SSZ 16640
#define AT_SMEM (16384 + 3*16640)

__global__ __launch_bounds__(256, 1)
void attn_mma(const __half* __restrict__ q16, const __half* __restrict__ k16,
              const __half* __restrict__ v16, const float* __restrict__ mask,
              __half* __restrict__ c16) {
    extern __shared__ char smv[];
    const uint32_t sb = s2u(smv);
    const int tid = threadIdx.x, lane = tid & 31, wid = tid >> 5;
    const int b = blockIdx.y >> 4, h = blockIdx.y & 15;
    const int q0 = blockIdx.x << 7;
    const size_t hoff = (size_t)h * 64;

    // Q tile: 128 rows x 64 cols fp16
    for (int i = tid; i < 1024; i += 256) {
        const int row = i >> 3, cc = i & 7;
        cpa(sb + AT_Q + swz((uint32_t)(row*128 + cc*16)),
            q16 + (size_t)(b*SS + q0 + row)*DD + hoff + cc*8);
    }
    for (int sidx = 0; sidx < 2; sidx++) {
        const int kt = sidx << 6;
        const uint32_t base = sb + AT_ST + (uint32_t)sidx * AT_SSZ;
        for (int i = tid; i < 1024; i += 256) {
            const int t = i >> 9, idx = i & 511, row = idx >> 3, cc = idx & 7;
            const __half* src = (t ? v16 : k16) + (size_t)(b*SS + kt + row)*DD + hoff + cc*8;
            cpa(base + t*8192 + swz((uint32_t)(row*128 + cc*16)), src);
        }
        if (tid < 16) cpa(base + 16384 + tid*16, mask + (size_t)b*SS + kt + tid*4);
        asm volatile("cp.async.commit_group;" ::: "memory");
    }

    uint32_t qf[4][4];
    float o[8][4], lacc[4];
    float mL0 = -1e30f, mL1 = -1e30f;
#pragma unroll
    for (int nt = 0; nt < 8; nt++) { o[nt][0]=o[nt][1]=o[nt][2]=o[nt][3]=0.f; }
    lacc[0]=lacc[1]=lacc[2]=lacc[3]=0.f;
    const uint32_t ones2[2] = {0x3C003C00u, 0x3C003C00u};

    for (int c = 0; c < SS/64; c++) {
        if (c + 2 < SS/64) {
            const int kt = (c + 2) << 6;
            const uint32_t base = sb + AT_ST + (uint32_t)((c+2) % 3) * AT_SSZ;
            for (int i = tid; i < 1024; i += 256) {
                const int t = i >> 9, idx = i & 511, row = idx >> 3, cc = idx & 7;
                const __half* src = (t ? v16 : k16) + (size_t)(b*SS + kt + row)*DD + hoff + cc*8;
                cpa(base + t*8192 + swz((uint32_t)(row*128 + cc*16)), src);
            }
            if (tid < 16) cpa(base + 16384 + tid*16, mask + (size_t)b*SS + kt + tid*4);
        }
        asm volatile("cp.async.commit_group;" ::: "memory");
        asm volatile("cp.async.wait_group 2;" ::: "memory");
        __syncthreads();

        if (c == 0) {
#pragma unroll
            for (int ks = 0; ks < 4; ks++) {
                const int row = wid*16 + (lane & 15);
                const int colb = (ks*16 + ((lane >> 4) << 3)) * 2;
                ldsm4(qf[ks], sb + AT_Q + swz((uint32_t)(row*128 + colb)));
            }
        }

        const uint32_t soff = AT_ST + (uint32_t)(c % 3) * AT_SSZ;
        const uint32_t st = sb + soff;
        float S[8][4];
#pragma unroll
        for (int nt = 0; nt < 8; nt++) { S[nt][0]=S[nt][1]=S[nt][2]=S[nt][3]=0.f; }
#pragma unroll
        for (int ks = 0; ks < 4; ks++) {
            uint32_t kb[8][2];
#pragma unroll
            for (int p = 0; p < 4; p++) {
                const int row = p*16 + (lane & 7) + ((lane >> 4) << 3);
                const int colb = (ks*16 + (((lane >> 3) & 1) << 3)) * 2;
                uint32_t t4[4];
                ldsm4(t4, st + swz((uint32_t)(row*128 + colb)));
                kb[2*p][0]=t4[0]; kb[2*p][1]=t4[1]; kb[2*p+1][0]=t4[2]; kb[2*p+1][1]=t4[3];
            }
#pragma unroll
            for (int nt = 0; nt < 8; nt++)
                mmaf16(S[nt], qf[ks], kb[nt]);
        }
#pragma unroll
        for (int nt = 0; nt < 8; nt++) {
            const float2 mv = *(const float2*)(smv + soff + 16384 + (8*nt + 2*(lane&3))*4);
            S[nt][0] = fmaf(S[nt][0], 0.125f, mv.x);
            S[nt][1] = fmaf(S[nt][1], 0.125f, mv.y);
            S[nt][2] = fmaf(S[nt][2], 0.125f, mv.x);
            S[nt][3] = fmaf(S[nt][3], 0.125f, mv.y);
        }
        float mx0 = -1e30f, mx1 = -1e30f;
#pragma unroll
        for (int nt = 0; nt < 8; nt++) {
            mx0 = fmaxf(mx0, fmaxf(S[nt][0], S[nt][1]));
            mx1 = fmaxf(mx1, fmaxf(S[nt][2], S[nt][3]));
        }
        mx0 = fmaxf(mx0, __shfl_xor_sync(~0u, mx0, 1));
        mx0 = fmaxf(mx0, __shfl_xor_sync(~0u, mx0, 2));
        mx1 = fmaxf(mx1, __shfl_xor_sync(~0u, mx1, 1));
        mx1 = fmaxf(mx1, __shfl_xor_sync(~0u, mx1, 2));
        const float mLn0 = fmaxf(mL0, mx0 * L2E);
        const float mLn1 = fmaxf(mL1, mx1 * L2E);
        const float corr0 = exp2f(mL0 - mLn0);
        const float corr1 = exp2f(mL1 - mLn1);
        mL0 = mLn0; mL1 = mLn1;
        lacc[0] *= corr0; lacc[1] *= corr0; lacc[2] *= corr1; lacc[3] *= corr1;
#pragma unroll
        for (int nt = 0; nt < 8; nt++) {
            o[nt][0] *= corr0; o[nt][1] *= corr0; o[nt][2] *= corr1; o[nt][3] *= corr1;
        }
        uint32_t pf[4][4];
#pragma unroll
        for (int j = 0; j < 4; j++) {
            pf[j][0] = exp2_pack(fmaf(S[2*j][1],   L2E, -mL0), fmaf(S[2*j][0],   L2E, -mL0));
            pf[j][1] = exp2_pack(fmaf(S[2*j][3],   L2E, -mL1), fmaf(S[2*j][2],   L2E, -mL1));
            pf[j][2] = exp2_pack(fmaf(S[2*j+1][1], L2E, -mL0), fmaf(S[2*j+1][0], L2E, -mL0));
            pf[j][3] = exp2_pack(fmaf(S[2*j+1][3], L2E, -mL1), fmaf(S[2*j+1][2], L2E, -mL1));
        }
#pragma unroll
        for (int j = 0; j < 4; j++) mmaf16(lacc, pf[j], ones2);
#pragma unroll
        for (int j = 0; j < 4; j++) {
            const int krow = j*16 + (lane & 15);
#pragma unroll
            for (int pp = 0; pp < 4; pp++) {
                const int colb = (pp*16 + ((lane >> 4) << 3)) * 2;
                uint32_t vf[4];
                ldsm4t(vf, st + 8192 + swz((uint32_t)(krow*128 + colb)));
                mmaf16(o[2*pp],   pf[j], vf);
                mmaf16(o[2*pp+1], pf[j], vf + 2);
            }
        }
        __syncthreads();
    }

    const float inv0 = 1.0f / lacc[0];
    const float inv1 = 1.0f / lacc[2];
    const size_t r0 = (size_t)(b*SS + q0 + wid*16 + (lane >> 2));
    const size_t r1 = r0 + 8;
#pragma unroll
    for (int nt = 0; nt < 8; nt++) {
        const size_t col = hoff + 8*nt + 2*(lane & 3);
        *(__half2*)&c16[r0*DD + col] = __halves2half2(
            __float2half_rn(o[nt][0]*inv0), __float2half_rn(o[nt][1]*inv0));
        *(__half2*)&c16[r1*DD + col] = __halves2half2(
            __float2half_rn(o[nt][2]*inv1), __float2half_rn(o[nt][3]*inv1));
    }
}

// ---- LayerNorm (optionally emits fp16 of its output) ----
__device__ __forceinline__ float block_sum_256(float v) {
    __shared__ float red[8];
    const int lane = threadIdx.x & 31, w = threadIdx.x >> 5;
#pragma unroll
    for (int off = 16; off; off >>= 1) v += __shfl_xor_sync(0xffffffffu, v, off);
    __syncthreads();
    if (lane == 0) red[w] = v;
    __syncthreads();
    return red[0]+red[1]+red[2]+red[3]+red[4]+red[5]+red[6]+red[7];
}
__global__ __launch_bounds__(256)
void ln_kernel(const float* __restrict__ Y, const float* __restrict__ R,
               const float* __restrict__ g, const float* __restrict__ bta,
               float* __restrict__ out, __half* __restrict__ h16) {
    const int row = blockIdx.x, tid = threadIdx.x;
    float4 v = ((const float4*)(Y + (size_t)row * DD))[tid];
    const float4 r = ((const float4*)(R + (size_t)row * DD))[tid];
    v.x += r.x; v.y += r.y; v.z += r.z; v.w += r.w;
    const float mean = block_sum_256(v.x + v.y + v.z + v.w) * (1.0f/1024.0f);
    const float dx = v.x-mean, dy = v.y-mean, dz = v.z-mean, dw = v.w-mean;
    const float rstd = rsqrtf(block_sum_256(dx*dx + dy*dy + dz*dz + dw*dw) * (1.0f/1024.0f) + 1e-12f);
    const float4 gg = ((const float4*)g)[tid];
    const float4 bb = ((const float4*)bta)[tid];
    float4 o;
    o.x = dx*rstd*gg.x + bb.x; o.y = dy*rstd*gg.y + bb.y;
    o.z = dz*rstd*gg.z + bb.z; o.w = dw*rstd*gg.w + bb.w;
    ((float4*)(out + (size_t)row * DD))[tid] = o;
    if (h16) {
        ((__half2*)(h16 + (size_t)row * DD))[2*tid] =
            __halves2half2(__float2half_rn(o.x), __float2half_rn(o.y));
        ((__half2*)(h16 + (size_t)row * DD))[2*tid+1] =
            __halves2half2(__float2half_rn(o.z), __float2half_rn(o.w));
    }
}

extern "C" void kernel_launch(void* const* d_in, const int* in_sizes, int n_in,
                              void* d_out, int out_size) {
    const float* x    = (const float*)d_in[0];
    const float* mask = (const float*)d_in[1];
    const float* Wq = (const float*)d_in[2];  const float* bq = (const float*)d_in[3];
    const float* Wk = (const float*)d_in[4];  const float* bk = (const float*)d_in[5];
    const float* Wv = (const float*)d_in[6];  const float* bv = (const float*)d_in[7];
    const float* Wo = (const float*)d_in[8];  const float* bo = (const float*)d_in[9];
    const float* ln1g = (const float*)d_in[10]; const float* ln1b = (const float*)d_in[11];
    const float* Wi = (const float*)d_in[12]; const float* bi = (const float*)d_in[13];
    const float* Wo2 = (const float*)d_in[14]; const float* bo2 = (const float*)d_in[15];
    const float* ln2g = (const float*)d_in[16]; const float* ln2b = (const float*)d_in[17];
    float* out = (float*)d_out;

    float *tmp, *res, *b3;
    __half *x16, *ln16, *c16, *f16, *q16, *k16, *v16, *wh;
    cudaGetSymbolAddress((void**)&tmp, g_tmp);
    cudaGetSymbolAddress((void**)&res, g_res);
    cudaGetSymbolAddress((void**)&b3, g_b3);
    cudaGetSymbolAddress((void**)&x16, g_x16);
    cudaGetSymbolAddress((void**)&ln16, g_ln16);
    cudaGetSymbolAddress((void**)&c16, g_c16);
    cudaGetSymbolAddress((void**)&f16, g_f16);
    cudaGetSymbolAddress((void**)&q16, g_q16);
    cudaGetSymbolAddress((void**)&k16, g_k16);
    cudaGetSymbolAddress((void**)&v16, g_v16);
    cudaGetSymbolAddress((void**)&wh, g_wh);

    cudaFuncSetAttribute(gemm_tc, cudaFuncAttributeMaxDynamicSharedMemorySize, GSMEM);
    cudaFuncSetAttribute(attn_mma, cudaFuncAttributeMaxDynamicSharedMemorySize, AT_SMEM);

    const dim3 tblk(32, 8);
    wconv_kernel<<<dim3(32, 32),  tblk>>>(Wq,  DD,   DD,   wh + W_QKV);
    wconv_kernel<<<dim3(32, 32),  tblk>>>(Wk,  DD,   DD,   wh + W_QKV + 1048576u);
    wconv_kernel<<<dim3(32, 32),  tblk>>>(Wv,  DD,   DD,   wh + W_QKV + 2097152u);
    wconv_kernel<<<dim3(32, 32),  tblk>>>(Wo,  DD,   DD,   wh + W_O);
    wconv_kernel<<<dim3(128, 32), tblk>>>(Wi,  DFFN, DD,   wh + W_I);
    wconv_kernel<<<dim3(32, 128), tblk>>>(Wo2, DD,   DFFN, wh + W_O2);
    pack3_kernel<<<3, 1024>>>(bq, bk, bv, b3);

    split16_kernel<<<2048, 256>>>(x, x16, MM * DD / 4);
    gemm_tc<<<dim3(QKVW/128, MM/128), 256, GSMEM>>>(x16, wh + W_QKV, b3,
        0, 0, q16, k16, v16, QKVW, DD, 0, 2);
    attn_mma<<<dim3(SS/128, BB*16), 256, AT_SMEM>>>(q16, k16, v16, mask, c16);
    gemm_tc<<<dim3(DD/128, MM/128), 256, GSMEM>>>(c16, wh + W_O, bo,
        tmp, 0, 0, 0, 0, DD, DD, 0, 0);
    ln_kernel<<<MM, 256>>>(tmp, x, ln1g, ln1b, res, ln16);
    gemm_tc<<<dim3(DFFN/128, MM/128), 256, GSMEM>>>(ln16, wh + W_I, bi,
        0, f16, 0, 0, 0, DFFN, DD, 1, 1);
    gemm_tc<<<dim3(DD/128, MM/128), 256, GSMEM>>>(f16, wh + W_O2, bo2,
        tmp, 0, 0, 0, 0, DD, DFFN, 0, 0);
    ln_kernel<<<MM, 256>>>(tmp, res, ln2g, ln2b, out, 0);
}

// round 11
// speedup vs baseline: 3.6704x; 1.1994x over previous
#include <cuda_runtime.h>
#include <cuda_bf16.h>
#include <cuda_fp16.h>
#include <math.h>
#include <stdint.h>

#define BB 4
#define SS 2048
#define DD 1024
#define DFFN 4096
#define MM (BB*SS)
#define QKVW 3072
#define L2E 1.44269504088896f

__device__ float g_tmp[(size_t)MM * DD];
__device__ float g_res[(size_t)MM * DD];
__device__ __half g_x16[(size_t)MM * DD];
__device__ __half g_ln16[(size_t)MM * DD];
__device__ __half g_c16[(size_t)MM * DD];
__device__ __half g_f16[(size_t)MM * DFFN];
__device__ __half g_q16[(size_t)MM * DD];
__device__ __half g_k16[(size_t)MM * DD];
__device__ __half g_v16[(size_t)MM * DD];
#define W_QKV 0u
#define W_O   (3u*1024*1024)
#define W_I   (4u*1024*1024)
#define W_O2  (8u*1024*1024)
__device__ __half g_wh[12u*1024*1024];
__device__ float g_b3[QKVW];

__device__ __forceinline__ float gelu_f(float x) {
    return 0.5f * x * (1.0f + erff(x * 0.70710678118654752f));
}
__device__ __forceinline__ uint32_t s2u(const void* p) {
    uint32_t a;
    asm("{ .reg .u64 t; cvta.to.shared.u64 t, %1; cvt.u32.u64 %0, t; }" : "=r"(a) : "l"(p));
    return a;
}
__device__ __forceinline__ uint32_t swz(uint32_t off) {
    return off ^ (((off >> 7) & 7u) << 4);
}
__device__ __forceinline__ void cpa(uint32_t dst, const void* src) {
    asm volatile("cp.async.cg.shared.global [%0], [%1], 16;" :: "r"(dst), "l"(src));
}
__device__ __forceinline__ void ldsm4(uint32_t* r, uint32_t addr) {
    asm volatile("ldmatrix.sync.aligned.m8n8.x4.shared.b16 {%0,%1,%2,%3}, [%4];"
        : "=r"(r[0]), "=r"(r[1]), "=r"(r[2]), "=r"(r[3]) : "r"(addr));
}
__device__ __forceinline__ void ldsm4t(uint32_t* r, uint32_t addr) {
    asm volatile("ldmatrix.sync.aligned.m8n8.x4.trans.shared.b16 {%0,%1,%2,%3}, [%4];"
        : "=r"(r[0]), "=r"(r[1]), "=r"(r[2]), "=r"(r[3]) : "r"(addr));
}
__device__ __forceinline__ void mmaf16(float* d, const uint32_t* a, const uint32_t* b) {
    asm volatile("mma.sync.aligned.m16n8k16.row.col.f32.f16.f16.f32 "
        "{%0,%1,%2,%3}, {%4,%5,%6,%7}, {%8,%9}, {%0,%1,%2,%3};"
        : "+f"(d[0]), "+f"(d[1]), "+f"(d[2]), "+f"(d[3])
        : "r"(a[0]), "r"(a[1]), "r"(a[2]), "r"(a[3]), "r"(b[0]), "r"(b[1]));
}
// MUFU f16x2 exp2: pack (even->lo, odd->hi) then 2^x on both halves
__device__ __forceinline__ uint32_t exp2_pack(float odd, float even) {
    uint32_t p, r;
    asm("cvt.rn.f16x2.f32 %0, %1, %2;" : "=r"(p) : "f"(odd), "f"(even));
    asm("ex2.approx.f16x2 %0, %1;" : "=r"(r) : "r"(p));
    return r;
}

// W [K,N] fp32 -> [N,K] fp16
__global__ __launch_bounds__(256)
void wconv_kernel(const float* __restrict__ W, int N, int K, __half* __restrict__ hi) {
    __shared__ float t[32][33];
    const int tx = threadIdx.x, ty = threadIdx.y;
    const int n0 = blockIdx.x * 32, k0 = blockIdx.y * 32;
    for (int j = ty; j < 32; j += 8) t[j][tx] = W[(size_t)(k0 + j) * N + n0 + tx];
    __syncthreads();
    for (int j = ty; j < 32; j += 8)
        hi[(size_t)(n0 + j) * K + k0 + tx] = __float2half_rn(t[tx][j]);
}

// fp32 -> fp16
__global__ __launch_bounds__(256)
void split16_kernel(const float* __restrict__ in, __half* __restrict__ o16, int n4) {
    for (int i = blockIdx.x * 256 + threadIdx.x; i < n4; i += gridDim.x * 256) {
        const float4 v = ((const float4*)in)[i];
        ((__half2*)o16)[2*i+0] = __halves2half2(__float2half_rn(v.x), __float2half_rn(v.y));
        ((__half2*)o16)[2*i+1] = __halves2half2(__float2half_rn(v.z), __float2half_rn(v.w));
    }
}

__global__ void pack3_kernel(const float* a, const float* b, const float* c, float* o) {
    const float* s = (blockIdx.x == 0) ? a : (blockIdx.x == 1) ? b : c;
    o[blockIdx.x * 1024 + threadIdx.x] = s[threadIdx.x];
}

// ---- fp16 GEMM: C[M,N] = A16[M,K] @ B16[N,K]^T + bias ----
// CTA 128x128, BK=64, 3-stage cp.async, occupancy 2.
#define STG_B 32768
#define T_A  0
#define T_B  16384
#define GSMEM (3*STG_B)

__device__ __forceinline__ void load_stage(uint32_t sbase,
    const __half* __restrict__ A, const __half* __restrict__ B,
    int K, int m0, int n0, int kb) {
    for (int i = threadIdx.x; i < 1024; i += 256) {
        const int row = i >> 3, cc = (i & 7) << 3;
        const uint32_t so = swz((uint32_t)(row * 128 + cc * 2));
        cpa(sbase + T_A + so, A + (size_t)(m0 + row) * K + kb + cc);
        cpa(sbase + T_B + so, B + (size_t)(n0 + row) * K + kb + cc);
    }
}

// mode 0: Cf fp32. mode 1: C16 fp16 (+act). mode 2: q/k/v fp16 out.
__global__ __launch_bounds__(256, 2)
void gemm_tc(const __half* __restrict__ A, const __half* __restrict__ B,
             const float* __restrict__ bias, float* __restrict__ Cf,
             __half* __restrict__ C16,
             __half* __restrict__ Q16, __half* __restrict__ K16, __half* __restrict__ V16,
             int N, int K, int act, int mode) {
    extern __shared__ char smv[];
    const uint32_t sb = s2u(smv);
    const int tid = threadIdx.x, lane = tid & 31, wid = tid >> 5;
    const int wm = wid & 3, wn = wid >> 2;
    const int m0 = blockIdx.y << 7, n0 = blockIdx.x << 7;
    const int nc = K >> 6;

    float acc[2][8][4];
#pragma unroll
    for (int i = 0; i < 2; i++)
#pragma unroll
        for (int j = 0; j < 8; j++)
#pragma unroll
            for (int q = 0; q < 4; q++) acc[i][j][q] = 0.0f;

    load_stage(sb, A, B, K, m0, n0, 0);
    asm volatile("cp.async.commit_group;" ::: "memory");
    load_stage(sb + STG_B, A, B, K, m0, n0, 64);
    asm volatile("cp.async.commit_group;" ::: "memory");

    const int a_r = (lane & 15);
    const int a_c = (lane >> 4) << 3;
    const int b_r = (lane & 7) + ((lane >> 4) << 3);
    const int b_c = ((lane >> 3) & 1) << 3;

    for (int c = 0; c < nc; c++) {
        if (c + 2 < nc)
            load_stage(sb + (uint32_t)((c + 2) % 3) * STG_B, A, B, K, m0, n0, (c + 2) << 6);
        asm volatile("cp.async.commit_group;" ::: "memory");
        asm volatile("cp.async.wait_group 2;" ::: "memory");
        __syncthreads();

        const uint32_t st = sb + (uint32_t)(c % 3) * STG_B;
#pragma unroll
        for (int ks = 0; ks < 4; ks++) {
            uint32_t af[2][4], bf[8][2];
#pragma unroll
            for (int mt = 0; mt < 2; mt++) {
                const uint32_t off = swz((uint32_t)((wm*32 + mt*16 + a_r)*128 + (ks*16 + a_c)*2));
                ldsm4(af[mt], st + T_A + off);
            }
#pragma unroll
            for (int p = 0; p < 4; p++) {
                const uint32_t off = swz((uint32_t)((wn*64 + p*16 + b_r)*128 + (ks*16 + b_c)*2));
                uint32_t t4[4];
                ldsm4(t4, st + T_B + off);
                bf[2*p][0]=t4[0]; bf[2*p][1]=t4[1]; bf[2*p+1][0]=t4[2]; bf[2*p+1][1]=t4[3];
            }
#pragma unroll
            for (int mt = 0; mt < 2; mt++)
#pragma unroll
                for (int nt = 0; nt < 8; nt++)
                    mmaf16(acc[mt][nt], af[mt], bf[nt]);
        }
        __syncthreads();
    }

    const int rbase = m0 + wm * 32 + (lane >> 2);
    const int cbase = n0 + wn * 64 + ((lane & 3) << 1);
    const int region = n0 >> 10;
#pragma unroll
    for (int mt = 0; mt < 2; mt++) {
#pragma unroll
        for (int nt = 0; nt < 8; nt++) {
            const int col = cbase + nt * 8;
            const float2 bv = *(const float2*)&bias[col];
            float v0 = acc[mt][nt][0] + bv.x, v1 = acc[mt][nt][1] + bv.y;
            float v2 = acc[mt][nt][2] + bv.x, v3 = acc[mt][nt][3] + bv.y;
            if (act) { v0 = gelu_f(v0); v1 = gelu_f(v1); v2 = gelu_f(v2); v3 = gelu_f(v3); }
            const size_t r0 = (size_t)(rbase + mt * 16);
            const size_t r1 = r0 + 8;
            if (mode == 0) {
                *(float2*)&Cf[r0 * N + col] = make_float2(v0, v1);
                *(float2*)&Cf[r1 * N + col] = make_float2(v2, v3);
            } else if (mode == 1) {
                *(__half2*)&C16[r0 * N + col] = __halves2half2(__float2half_rn(v0), __float2half_rn(v1));
                *(__half2*)&C16[r1 * N + col] = __halves2half2(__float2half_rn(v2), __float2half_rn(v3));
            } else {
                const size_t cl_ = (size_t)(col - (region << 10));
                __half* D = (region == 0) ? Q16 : (region == 1) ? K16 : V16;
                *(__half2*)&D[r0 * DD + cl_] = __halves2half2(__float2half_rn(v0), __float2half_rn(v1));
                *(__half2*)&D[r1 * DD + cl_] = __halves2half2(__float2half_rn(v2), __float2half_rn(v3));
            }
        }
    }
}

// ---- fp16 flash attention: 128 q-rows/CTA, MUFU f16x2 exp, occupancy 2 ----
#define AT_Q 0
#define AT_ST 16384
#define AT_SSZ 16640
#define AT_SMEM (16384 + 3*16640)

__global__ __launch_bounds__(256, 2)
void attn_mma(const __half* __restrict__ q16, const __half* __restrict__ k16,
              const __half* __restrict__ v16, const float* __restrict__ mask,
              __half* __restrict__ c16) {
    extern __shared__ char smv[];
    const uint32_t sb = s2u(smv);
    const int tid = threadIdx.x, lane = tid & 31, wid = tid >> 5;
    const int b = blockIdx.y >> 4, h = blockIdx.y & 15;
    const int q0 = blockIdx.x << 7;
    const size_t hoff = (size_t)h * 64;

    // Q tile: 128 rows x 64 cols fp16
    for (int i = tid; i < 1024; i += 256) {
        const int row = i >> 3, cc = i & 7;
        cpa(sb + AT_Q + swz((uint32_t)(row*128 + cc*16)),
            q16 + (size_t)(b*SS + q0 + row)*DD + hoff + cc*8);
    }
    for (int sidx = 0; sidx < 2; sidx++) {
        const int kt = sidx << 6;
        const uint32_t base = sb + AT_ST + (uint32_t)sidx * AT_SSZ;
        for (int i = tid; i < 1024; i += 256) {
            const int t = i >> 9, idx = i & 511, row = idx >> 3, cc = idx & 7;
            const __half* src = (t ? v16 : k16) + (size_t)(b*SS + kt + row)*DD + hoff + cc*8;
            cpa(base + t*8192 + swz((uint32_t)(row*128 + cc*16)), src);
        }
        if (tid < 16) cpa(base + 16384 + tid*16, mask + (size_t)b*SS + kt + tid*4);
        asm volatile("cp.async.commit_group;" ::: "memory");
    }

    uint32_t qf[4][4];
    float o[8][4], lacc[4];
    float mL0 = -1e30f, mL1 = -1e30f;
#pragma unroll
    for (int nt = 0; nt < 8; nt++) { o[nt][0]=o[nt][1]=o[nt][2]=o[nt][3]=0.f; }
    lacc[0]=lacc[1]=lacc[2]=lacc[3]=0.f;
    const uint32_t ones2[2] = {0x3C003C00u, 0x3C003C00u};

    for (int c = 0; c < SS/64; c++) {
        if (c + 2 < SS/64) {
            const int kt = (c + 2) << 6;
            const uint32_t base = sb + AT_ST + (uint32_t)((c+2) % 3) * AT_SSZ;
            for (int i = tid; i < 1024; i += 256) {
                const int t = i >> 9, idx = i & 511, row = idx >> 3, cc = idx & 7;
                const __half* src = (t ? v16 : k16) + (size_t)(b*SS + kt + row)*DD + hoff + cc*8;
                cpa(base + t*8192 + swz((uint32_t)(row*128 + cc*16)), src);
            }
            if (tid < 16) cpa(base + 16384 + tid*16, mask + (size_t)b*SS + kt + tid*4);
        }
        asm volatile("cp.async.commit_group;" ::: "memory");
        asm volatile("cp.async.wait_group 2;" ::: "memory");
        __syncthreads();

        if (c == 0) {
#pragma unroll
            for (int ks = 0; ks < 4; ks++) {
                const int row = wid*16 + (lane & 15);
                const int colb = (ks*16 + ((lane >> 4) << 3)) * 2;
                ldsm4(qf[ks], sb + AT_Q + swz((uint32_t)(row*128 + colb)));
            }
        }

        const uint32_t soff = AT_ST + (uint32_t)(c % 3) * AT_SSZ;
        const uint32_t st = sb + soff;
        float S[8][4];
#pragma unroll
        for (int nt = 0; nt < 8; nt++) { S[nt][0]=S[nt][1]=S[nt][2]=S[nt][3]=0.f; }
#pragma unroll
        for (int ks = 0; ks < 4; ks++) {
            uint32_t kb[8][2];
#pragma unroll
            for (int p = 0; p < 4; p++) {
                const int row = p*16 + (lane & 7) + ((lane >> 4) << 3);
                const int colb = (ks*16 + (((lane >> 3) & 1) << 3)) * 2;
                uint32_t t4[4];
                ldsm4(t4, st + swz((uint32_t)(row*128 + colb)));
                kb[2*p][0]=t4[0]; kb[2*p][1]=t4[1]; kb[2*p+1][0]=t4[2]; kb[2*p+1][1]=t4[3];
            }
#pragma unroll
            for (int nt = 0; nt < 8; nt++)
                mmaf16(S[nt], qf[ks], kb[nt]);
        }
#pragma unroll
        for (int nt = 0; nt < 8; nt++) {
            const float2 mv = *(const float2*)(smv + soff + 16384 + (8*nt + 2*(lane&3))*4);
            S[nt][0] = fmaf(S[nt][0], 0.125f, mv.x);
            S[nt][1] = fmaf(S[nt][1], 0.125f, mv.y);
            S[nt][2] = fmaf(S[nt][2], 0.125f, mv.x);
            S[nt][3] = fmaf(S[nt][3], 0.125f, mv.y);
        }
        float mx0 = -1e30f, mx1 = -1e30f;
#pragma unroll
        for (int nt = 0; nt < 8; nt++) {
            mx0 = fmaxf(mx0, fmaxf(S[nt][0], S[nt][1]));
            mx1 = fmaxf(mx1, fmaxf(S[nt][2], S[nt][3]));
        }
        mx0 = fmaxf(mx0, __shfl_xor_sync(~0u, mx0, 1));
        mx0 = fmaxf(mx0, __shfl_xor_sync(~0u, mx0, 2));
        mx1 = fmaxf(mx1, __shfl_xor_sync(~0u, mx1, 1));
        mx1 = fmaxf(mx1, __shfl_xor_sync(~0u, mx1, 2));
        const float mLn0 = fmaxf(mL0, mx0 * L2E);
        const float mLn1 = fmaxf(mL1, mx1 * L2E);
        const float corr0 = exp2f(mL0 - mLn0);
        const float corr1 = exp2f(mL1 - mLn1);
        mL0 = mLn0; mL1 = mLn1;
        lacc[0] *= corr0; lacc[1] *= corr0; lacc[2] *= corr1; lacc[3] *= corr1;
#pragma unroll
        for (int nt = 0; nt < 8; nt++) {
            o[nt][0] *= corr0; o[nt][1] *= corr0; o[nt][2] *= corr1; o[nt][3] *= corr1;
        }
        uint32_t pf[4][4];
#pragma unroll
        for (int j = 0; j < 4; j++) {
            pf[j][0] = exp2_pack(fmaf(S[2*j][1],   L2E, -mL0), fmaf(S[2*j][0],   L2E, -mL0));
            pf[j][1] = exp2_pack(fmaf(S[2*j][3],   L2E, -mL1), fmaf(S[2*j][2],   L2E, -mL1));
            pf[j][2] = exp2_pack(fmaf(S[2*j+1][1], L2E, -mL0), fmaf(S[2*j+1][0], L2E, -mL0));
            pf[j][3] = exp2_pack(fmaf(S[2*j+1][3], L2E, -mL1), fmaf(S[2*j+1][2], L2E, -mL1));
        }
#pragma unroll
        for (int j = 0; j < 4; j++) mmaf16(lacc, pf[j], ones2);
#pragma unroll
        for (int j = 0; j < 4; j++) {
            const int krow = j*16 + (lane & 15);
#pragma unroll
            for (int pp = 0; pp < 4; pp++) {
                const int colb = (pp*16 + ((lane >> 4) << 3)) * 2;
                uint32_t vf[4];
                ldsm4t(vf, st + 8192 + swz((uint32_t)(krow*128 + colb)));
                mmaf16(o[2*pp],   pf[j], vf);
                mmaf16(o[2*pp+1], pf[j], vf + 2);
            }
        }
        __syncthreads();
    }

    const float inv0 = 1.0f / lacc[0];
    const float inv1 = 1.0f / lacc[2];
    const size_t r0 = (size_t)(b*SS + q0 + wid*16 + (lane >> 2));
    const size_t r1 = r0 + 8;
#pragma unroll
    for (int nt = 0; nt < 8; nt++) {
        const size_t col = hoff + 8*nt + 2*(lane & 3);
        *(__half2*)&c16[r0*DD + col] = __halves2half2(
            __float2half_rn(o[nt][0]*inv0), __float2half_rn(o[nt][1]*inv0));
        *(__half2*)&c16[r1*DD + col] = __halves2half2(
            __float2half_rn(o[nt][2]*inv1), __float2half_rn(o[nt][3]*inv1));
    }
}

// ---- LayerNorm (optionally emits fp16 of its output) ----
__device__ __forceinline__ float block_sum_256(float v) {
    __shared__ float red[8];
    const int lane = threadIdx.x & 31, w = threadIdx.x >> 5;
#pragma unroll
    for (int off = 16; off; off >>= 1) v += __shfl_xor_sync(0xffffffffu, v, off);
    __syncthreads();
    if (lane == 0) red[w] = v;
    __syncthreads();
    return red[0]+red[1]+red[2]+red[3]+red[4]+red[5]+red[6]+red[7];
}
__global__ __launch_bounds__(256)
void ln_kernel(const float* __restrict__ Y, const float* __restrict__ R,
               const float* __restrict__ g, const float* __restrict__ bta,
               float* __restrict__ out, __half* __restrict__ h16) {
    const int row = blockIdx.x, tid = threadIdx.x;
    float4 v = ((const float4*)(Y + (size_t)row * DD))[tid];
    const float4 r = ((const float4*)(R + (size_t)row * DD))[tid];
    v.x += r.x; v.y += r.y; v.z += r.z; v.w += r.w;
    const float mean = block_sum_256(v.x + v.y + v.z + v.w) * (1.0f/1024.0f);
    const float dx = v.x-mean, dy = v.y-mean, dz = v.z-mean, dw = v.w-mean;
    const float rstd = rsqrtf(block_sum_256(dx*dx + dy*dy + dz*dz + dw*dw) * (1.0f/1024.0f) + 1e-12f);
    const float4 gg = ((const float4*)g)[tid];
    const float4 bb = ((const float4*)bta)[tid];
    float4 o;
    o.x = dx*rstd*gg.x + bb.x; o.y = dy*rstd*gg.y + bb.y;
    o.z = dz*rstd*gg.z + bb.z; o.w = dw*rstd*gg.w + bb.w;
    ((float4*)(out + (size_t)row * DD))[tid] = o;
    if (h16) {
        ((__half2*)(h16 + (size_t)row * DD))[2*tid] =
            __halves2half2(__float2half_rn(o.x), __float2half_rn(o.y));
        ((__half2*)(h16 + (size_t)row * DD))[2*tid+1] =
            __halves2half2(__float2half_rn(o.z), __float2half_rn(o.w));
    }
}

extern "C" void kernel_launch(void* const* d_in, const int* in_sizes, int n_in,
                              void* d_out, int out_size) {
    const float* x    = (const float*)d_in[0];
    const float* mask = (const float*)d_in[1];
    const float* Wq = (const float*)d_in[2];  const float* bq = (const float*)d_in[3];
    const float* Wk = (const float*)d_in[4];  const float* bk = (const float*)d_in[5];
    const float* Wv = (const float*)d_in[6];  const float* bv = (const float*)d_in[7];
    const float* Wo = (const float*)d_in[8];  const float* bo = (const float*)d_in[9];
    const float* ln1g = (const float*)d_in[10]; const float* ln1b = (const float*)d_in[11];
    const float* Wi = (const float*)d_in[12]; const float* bi = (const float*)d_in[13];
    const float* Wo2 = (const float*)d_in[14]; const float* bo2 = (const float*)d_in[15];
    const float* ln2g = (const float*)d_in[16]; const float* ln2b = (const float*)d_in[17];
    float* out = (float*)d_out;

    float *tmp, *res, *b3;
    __half *x16, *ln16, *c16, *f16, *q16, *k16, *v16, *wh;
    cudaGetSymbolAddress((void**)&tmp, g_tmp);
    cudaGetSymbolAddress((void**)&res, g_res);
    cudaGetSymbolAddress((void**)&b3, g_b3);
    cudaGetSymbolAddress((void**)&x16, g_x16);
    cudaGetSymbolAddress((void**)&ln16, g_ln16);
    cudaGetSymbolAddress((void**)&c16, g_c16);
    cudaGetSymbolAddress((void**)&f16, g_f16);
    cudaGetSymbolAddress((void**)&q16, g_q16);
    cudaGetSymbolAddress((void**)&k16, g_k16);
    cudaGetSymbolAddress((void**)&v16, g_v16);
    cudaGetSymbolAddress((void**)&wh, g_wh);

    cudaFuncSetAttribute(gemm_tc, cudaFuncAttributeMaxDynamicSharedMemorySize, GSMEM);
    cudaFuncSetAttribute(attn_mma, cudaFuncAttributeMaxDynamicSharedMemorySize, AT_SMEM);

    const dim3 tblk(32, 8);
    wconv_kernel<<<dim3(32, 32),  tblk>>>(Wq,  DD,   DD,   wh + W_QKV);
    wconv_kernel<<<dim3(32, 32),  tblk>>>(Wk,  DD,   DD,   wh + W_QKV + 1048576u);
    wconv_kernel<<<dim3(32, 32),  tblk>>>(Wv,  DD,   DD,   wh + W_QKV + 2097152u);
    wconv_kernel<<<dim3(32, 32),  tblk>>>(Wo,  DD,   DD,   wh + W_O);
    wconv_kernel<<<dim3(128, 32), tblk>>>(Wi,  DFFN, DD,   wh + W_I);
    wconv_kernel<<<dim3(32, 128), tblk>>>(Wo2, DD,   DFFN, wh + W_O2);
    pack3_kernel<<<3, 1024>>>(bq, bk, bv, b3);

    split16_kernel<<<2048, 256>>>(x, x16, MM * DD / 4);
    gemm_tc<<<dim3(QKVW/128, MM/128), 256, GSMEM>>>(x16, wh + W_QKV, b3,
        0, 0, q16, k16, v16, QKVW, DD, 0, 2);
    attn_mma<<<dim3(SS/128, BB*16), 256, AT_SMEM>>>(q16, k16, v16, mask, c16);
    gemm_tc<<<dim3(DD/128, MM/128), 256, GSMEM>>>(c16, wh + W_O, bo,
        tmp, 0, 0, 0, 0, DD, DD, 0, 0);
    ln_kernel<<<MM, 256>>>(tmp, x, ln1g, ln1b, res, ln16);
    gemm_tc<<<dim3(DFFN/128, MM/128), 256, GSMEM>>>(ln16, wh + W_I, bi,
        0, f16, 0, 0, 0, DFFN, DD, 1, 1);
    gemm_tc<<<dim3(DD/128, MM/128), 256, GSMEM>>>(f16, wh + W_O2, bo2,
        tmp, 0, 0, 0, 0, DD, DFFN, 0, 0);
    ln_kernel<<<MM, 256>>>(tmp, res, ln2g, ln2b, out, 0);
}

// round 12
// speedup vs baseline: 3.7364x; 1.0180x over previous
#include <cuda_runtime.h>
#include <cuda_bf16.h>
#include <cuda_fp16.h>
#include <math.h>
#include <stdint.h>

#define BB 4
#define SS 2048
#define DD 1024
#define DFFN 4096
#define MM (BB*SS)
#define QKVW 3072
#define L2E 1.44269504088896f

__device__ float g_tmp[(size_t)MM * DD];
__device__ float g_res[(size_t)MM * DD];
__device__ __half g_x16[(size_t)MM * DD];
__device__ __half g_ln16[(size_t)MM * DD];
__device__ __half g_c16[(size_t)MM * DD];
__device__ __half g_f16[(size_t)MM * DFFN];
__device__ __half g_q16[(size_t)MM * DD];
__device__ __half g_k16[(size_t)MM * DD];
__device__ __half g_v16[(size_t)MM * DD];
#define W_QKV 0u
#define W_O   (3u*1024*1024)
#define W_I   (4u*1024*1024)
#define W_O2  (8u*1024*1024)
__device__ __half g_wh[12u*1024*1024];
__device__ float g_b3[QKVW];

__device__ __forceinline__ float gelu_f(float x) {
    return 0.5f * x * (1.0f + erff(x * 0.70710678118654752f));
}
__device__ __forceinline__ uint32_t s2u(const void* p) {
    uint32_t a;
    asm("{ .reg .u64 t; cvta.to.shared.u64 t, %1; cvt.u32.u64 %0, t; }" : "=r"(a) : "l"(p));
    return a;
}
__device__ __forceinline__ uint32_t swz(uint32_t off) {
    return off ^ (((off >> 7) & 7u) << 4);
}
__device__ __forceinline__ void cpa(uint32_t dst, const void* src) {
    asm volatile("cp.async.cg.shared.global [%0], [%1], 16;" :: "r"(dst), "l"(src));
}
__device__ __forceinline__ void ldsm4(uint32_t* r, uint32_t addr) {
    asm volatile("ldmatrix.sync.aligned.m8n8.x4.shared.b16 {%0,%1,%2,%3}, [%4];"
        : "=r"(r[0]), "=r"(r[1]), "=r"(r[2]), "=r"(r[3]) : "r"(addr));
}
__device__ __forceinline__ void ldsm4t(uint32_t* r, uint32_t addr) {
    asm volatile("ldmatrix.sync.aligned.m8n8.x4.trans.shared.b16 {%0,%1,%2,%3}, [%4];"
        : "=r"(r[0]), "=r"(r[1]), "=r"(r[2]), "=r"(r[3]) : "r"(addr));
}
__device__ __forceinline__ void mmaf16(float* d, const uint32_t* a, const uint32_t* b) {
    asm volatile("mma.sync.aligned.m16n8k16.row.col.f32.f16.f16.f32 "
        "{%0,%1,%2,%3}, {%4,%5,%6,%7}, {%8,%9}, {%0,%1,%2,%3};"
        : "+f"(d[0]), "+f"(d[1]), "+f"(d[2]), "+f"(d[3])
        : "r"(a[0]), "r"(a[1]), "r"(a[2]), "r"(a[3]), "r"(b[0]), "r"(b[1]));
}
// MUFU f16x2 exp2: pack (even->lo, odd->hi) then 2^x on both halves
__device__ __forceinline__ uint32_t exp2_pack(float odd, float even) {
    uint32_t p, r;
    asm("cvt.rn.f16x2.f32 %0, %1, %2;" : "=r"(p) : "f"(odd), "f"(even));
    asm("ex2.approx.f16x2 %0, %1;" : "=r"(r) : "r"(p));
    return r;
}

// ---- megaprep: 6 weight transposes + x->fp16 + bias pack, ONE launch ----
// blocks [0,1024) Wq | [1024,2048) Wk | [2048,3072) Wv | [3072,4096) Wo |
// [4096,8192) Wi | [8192,12288) Wo2 | [12288,14336) split16(x) | [14336,14339) pack3
__device__ __forceinline__ void wconv_tile(const float* __restrict__ W, int N, int K,
                                           __half* __restrict__ hi, int bx, int by,
                                           int tx, int ty) {
    __shared__ float t[32][33];
    const int n0 = bx * 32, k0 = by * 32;
    for (int j = ty; j < 32; j += 8) t[j][tx] = W[(size_t)(k0 + j) * N + n0 + tx];
    __syncthreads();
    for (int j = ty; j < 32; j += 8)
        hi[(size_t)(n0 + j) * K + k0 + tx] = __float2half_rn(t[tx][j]);
}

__global__ __launch_bounds__(256)
void megaprep_kernel(const float* __restrict__ Wq, const float* __restrict__ Wk,
                     const float* __restrict__ Wv, const float* __restrict__ Wo,
                     const float* __restrict__ Wi, const float* __restrict__ Wo2,
                     const float* __restrict__ x,
                     const float* __restrict__ bq, const float* __restrict__ bk,
                     const float* __restrict__ bv,
                     __half* __restrict__ wh, __half* __restrict__ x16,
                     float* __restrict__ b3) {
    const int b = blockIdx.x;
    const int tx = threadIdx.x & 31, ty = threadIdx.x >> 5;
    if (b < 4096) {
        const int which = b >> 10, idx = b & 1023;
        const int bx = idx & 31, by = idx >> 5;
        const float* W = (which == 0) ? Wq : (which == 1) ? Wk : (which == 2) ? Wv : Wo;
        __half* dst = wh + ((which < 3) ? (W_QKV + (uint32_t)which * 1048576u) : W_O);
        wconv_tile(W, DD, DD, dst, bx, by, tx, ty);
    } else if (b < 8192) {
        const int idx = b - 4096;
        wconv_tile(Wi, DFFN, DD, wh + W_I, idx & 127, idx >> 7, tx, ty);
    } else if (b < 12288) {
        const int idx = b - 8192;
        wconv_tile(Wo2, DD, DFFN, wh + W_O2, idx & 31, idx >> 5, tx, ty);
    } else if (b < 14336) {
        const int tid = threadIdx.x;
        for (int i = (b - 12288) * 256 + tid; i < MM * DD / 4; i += 2048 * 256) {
            const float4 v = ((const float4*)x)[i];
            ((__half2*)x16)[2*i+0] = __halves2half2(__float2half_rn(v.x), __float2half_rn(v.y));
            ((__half2*)x16)[2*i+1] = __halves2half2(__float2half_rn(v.z), __float2half_rn(v.w));
        }
    } else {
        const int which = b - 14336;
        const float* s = (which == 0) ? bq : (which == 1) ? bk : bv;
        for (int i = threadIdx.x; i < 1024; i += 256)
            b3[which * 1024 + i] = s[i];
    }
}

// ---- fp16 GEMM: C[M,N] = A16[M,K] @ B16[N,K]^T + bias ----
// CTA 128x128, BK=64, 3-stage cp.async, occupancy 2.
#define STG_B 32768
#define T_A  0
#define T_B  16384
#define GSMEM (3*STG_B)

__device__ __forceinline__ void load_stage(uint32_t sbase,
    const __half* __restrict__ A, const __half* __restrict__ B,
    int K, int m0, int n0, int kb) {
    for (int i = threadIdx.x; i < 1024; i += 256) {
        const int row = i >> 3, cc = (i & 7) << 3;
        const uint32_t so = swz((uint32_t)(row * 128 + cc * 2));
        cpa(sbase + T_A + so, A + (size_t)(m0 + row) * K + kb + cc);
        cpa(sbase + T_B + so, B + (size_t)(n0 + row) * K + kb + cc);
    }
}

// mode 0: Cf fp32. mode 1: C16 fp16 (+act). mode 2: q/k/v fp16 out.
__global__ __launch_bounds__(256, 2)
void gemm_tc(const __half* __restrict__ A, const __half* __restrict__ B,
             const float* __restrict__ bias, float* __restrict__ Cf,
             __half* __restrict__ C16,
             __half* __restrict__ Q16, __half* __restrict__ K16, __half* __restrict__ V16,
             int N, int K, int act, int mode) {
    extern __shared__ char smv[];
    const uint32_t sb = s2u(smv);
    const int tid = threadIdx.x, lane = tid & 31, wid = tid >> 5;
    const int wm = wid & 3, wn = wid >> 2;
    const int m0 = blockIdx.y << 7, n0 = blockIdx.x << 7;
    const int nc = K >> 6;

    float acc[2][8][4];
#pragma unroll
    for (int i = 0; i < 2; i++)
#pragma unroll
        for (int j = 0; j < 8; j++)
#pragma unroll
            for (int q = 0; q < 4; q++) acc[i][j][q] = 0.0f;

    load_stage(sb, A, B, K, m0, n0, 0);
    asm volatile("cp.async.commit_group;" ::: "memory");
    load_stage(sb + STG_B, A, B, K, m0, n0, 64);
    asm volatile("cp.async.commit_group;" ::: "memory");

    const int a_r = (lane & 15);
    const int a_c = (lane >> 4) << 3;
    const int b_r = (lane & 7) + ((lane >> 4) << 3);
    const int b_c = ((lane >> 3) & 1) << 3;

    for (int c = 0; c < nc; c++) {
        if (c + 2 < nc)
            load_stage(sb + (uint32_t)((c + 2) % 3) * STG_B, A, B, K, m0, n0, (c + 2) << 6);
        asm volatile("cp.async.commit_group;" ::: "memory");
        asm volatile("cp.async.wait_group 2;" ::: "memory");
        __syncthreads();

        const uint32_t st = sb + (uint32_t)(c % 3) * STG_B;
#pragma unroll
        for (int ks = 0; ks < 4; ks++) {
            uint32_t af[2][4], bf[8][2];
#pragma unroll
            for (int mt = 0; mt < 2; mt++) {
                const uint32_t off = swz((uint32_t)((wm*32 + mt*16 + a_r)*128 + (ks*16 + a_c)*2));
                ldsm4(af[mt], st + T_A + off);
            }
#pragma unroll
            for (int p = 0; p < 4; p++) {
                const uint32_t off = swz((uint32_t)((wn*64 + p*16 + b_r)*128 + (ks*16 + b_c)*2));
                uint32_t t4[4];
                ldsm4(t4, st + T_B + off);
                bf[2*p][0]=t4[0]; bf[2*p][1]=t4[1]; bf[2*p+1][0]=t4[2]; bf[2*p+1][1]=t4[3];
            }
#pragma unroll
            for (int mt = 0; mt < 2; mt++)
#pragma unroll
                for (int nt = 0; nt < 8; nt++)
                    mmaf16(acc[mt][nt], af[mt], bf[nt]);
        }
        __syncthreads();
    }

    const int rbase = m0 + wm * 32 + (lane >> 2);
    const int cbase = n0 + wn * 64 + ((lane & 3) << 1);
    const int region = n0 >> 10;
#pragma unroll
    for (int mt = 0; mt < 2; mt++) {
#pragma unroll
        for (int nt = 0; nt < 8; nt++) {
            const int col = cbase + nt * 8;
            const float2 bv = *(const float2*)&bias[col];
            float v0 = acc[mt][nt][0] + bv.x, v1 = acc[mt][nt][1] + bv.y;
            float v2 = acc[mt][nt][2] + bv.x, v3 = acc[mt][nt][3] + bv.y;
            if (act) { v0 = gelu_f(v0); v1 = gelu_f(v1); v2 = gelu_f(v2); v3 = gelu_f(v3); }
            const size_t r0 = (size_t)(rbase + mt * 16);
            const size_t r1 = r0 + 8;
            if (mode == 0) {
                *(float2*)&Cf[r0 * N + col] = make_float2(v0, v1);
                *(float2*)&Cf[r1 * N + col] = make_float2(v2, v3);
            } else if (mode == 1) {
                *(__half2*)&C16[r0 * N + col] = __halves2half2(__float2half_rn(v0), __float2half_rn(v1));
                *(__half2*)&C16[r1 * N + col] = __halves2half2(__float2half_rn(v2), __float2half_rn(v3));
            } else {
                const size_t cl_ = (size_t)(col - (region << 10));
                __half* D = (region == 0) ? Q16 : (region == 1) ? K16 : V16;
                *(__half2*)&D[r0 * DD + cl_] = __halves2half2(__float2half_rn(v0), __float2half_rn(v1));
                *(__half2*)&D[r1 * DD + cl_] = __halves2half2(__float2half_rn(v2), __float2half_rn(v3));
            }
        }
    }
}

// ---- fp16 flash attention: 128 q-rows/CTA, MUFU f16x2 exp, occupancy 2 ----
#define AT_Q 0
#define AT_ST 16384
#define AT_SSZ 16640
#define AT_SMEM (16384 + 3*16640)

__global__ __launch_bounds__(256, 2)
void attn_mma(const __half* __restrict__ q16, const __half* __restrict__ k16,
              const __half* __restrict__ v16, const float* __restrict__ mask,
              __half* __restrict__ c16) {
    extern __shared__ char smv[];
    const uint32_t sb = s2u(smv);
    const int tid = threadIdx.x, lane = tid & 31, wid = tid >> 5;
    const int b = blockIdx.y >> 4, h = blockIdx.y & 15;
    const int q0 = blockIdx.x << 7;
    const size_t hoff = (size_t)h * 64;

    for (int i = tid; i < 1024; i += 256) {
        const int row = i >> 3, cc = i & 7;
        cpa(sb + AT_Q + swz((uint32_t)(row*128 + cc*16)),
            q16 + (size_t)(b*SS + q0 + row)*DD + hoff + cc*8);
    }
    for (int sidx = 0; sidx < 2; sidx++) {
        const int kt = sidx << 6;
        const uint32_t base = sb + AT_ST + (uint32_t)sidx * AT_SSZ;
        for (int i = tid; i < 1024; i += 256) {
            const int t = i >> 9, idx = i & 511, row = idx >> 3, cc = idx & 7;
            const __half* src = (t ? v16 : k16) + (size_t)(b*SS + kt + row)*DD + hoff + cc*8;
            cpa(base + t*8192 + swz((uint32_t)(row*128 + cc*16)), src);
        }
        if (tid < 16) cpa(base + 16384 + tid*16, mask + (size_t)b*SS + kt + tid*4);
        asm volatile("cp.async.commit_group;" ::: "memory");
    }

    uint32_t qf[4][4];
    float o[8][4], lacc[4];
    float mL0 = -1e30f, mL1 = -1e30f;
#pragma unroll
    for (int nt = 0; nt < 8; nt++) { o[nt][0]=o[nt][1]=o[nt][2]=o[nt][3]=0.f; }
    lacc[0]=lacc[1]=lacc[2]=lacc[3]=0.f;
    const uint32_t ones2[2] = {0x3C003C00u, 0x3C003C00u};

    for (int c = 0; c < SS/64; c++) {
        if (c + 2 < SS/64) {
            const int kt = (c + 2) << 6;
            const uint32_t base = sb + AT_ST + (uint32_t)((c+2) % 3) * AT_SSZ;
            for (int i = tid; i < 1024; i += 256) {
                const int t = i >> 9, idx = i & 511, row = idx >> 3, cc = idx & 7;
                const __half* src = (t ? v16 : k16) + (size_t)(b*SS + kt + row)*DD + hoff + cc*8;
                cpa(base + t*8192 + swz((uint32_t)(row*128 + cc*16)), src);
            }
            if (tid < 16) cpa(base + 16384 + tid*16, mask + (size_t)b*SS + kt + tid*4);
        }
        asm volatile("cp.async.commit_group;" ::: "memory");
        asm volatile("cp.async.wait_group 2;" ::: "memory");
        __syncthreads();

        if (c == 0) {
#pragma unroll
            for (int ks = 0; ks < 4; ks++) {
                const int row = wid*16 + (lane & 15);
                const int colb = (ks*16 + ((lane >> 4) << 3)) * 2;
                ldsm4(qf[ks], sb + AT_Q + swz((uint32_t)(row*128 + colb)));
            }
        }

        const uint32_t soff = AT_ST + (uint32_t)(c % 3) * AT_SSZ;
        const uint32_t st = sb + soff;
        float S[8][4];
#pragma unroll
        for (int nt = 0; nt < 8; nt++) { S[nt][0]=S[nt][1]=S[nt][2]=S[nt][3]=0.f; }
#pragma unroll
        for (int ks = 0; ks < 4; ks++) {
            uint32_t kb[8][2];
#pragma unroll
            for (int p = 0; p < 4; p++) {
                const int row = p*16 + (lane & 7) + ((lane >> 4) << 3);
                const int colb = (ks*16 + (((lane >> 3) & 1) << 3)) * 2;
                uint32_t t4[4];
                ldsm4(t4, st + swz((uint32_t)(row*128 + colb)));
                kb[2*p][0]=t4[0]; kb[2*p][1]=t4[1]; kb[2*p+1][0]=t4[2]; kb[2*p+1][1]=t4[3];
            }
#pragma unroll
            for (int nt = 0; nt < 8; nt++)
                mmaf16(S[nt], qf[ks], kb[nt]);
        }
#pragma unroll
        for (int nt = 0; nt < 8; nt++) {
            const float2 mv = *(const float2*)(smv + soff + 16384 + (8*nt + 2*(lane&3))*4);
            S[nt][0] = fmaf(S[nt][0], 0.125f, mv.x);
            S[nt][1] = fmaf(S[nt][1], 0.125f, mv.y);
            S[nt][2] = fmaf(S[nt][2], 0.125f, mv.x);
            S[nt][3] = fmaf(S[nt][3], 0.125f, mv.y);
        }
        float mx0 = -1e30f, mx1 = -1e30f;
#pragma unroll
        for (int nt = 0; nt < 8; nt++) {
            mx0 = fmaxf(mx0, fmaxf(S[nt][0], S[nt][1]));
            mx1 = fmaxf(mx1, fmaxf(S[nt][2], S[nt][3]));
        }
        mx0 = fmaxf(mx0, __shfl_xor_sync(~0u, mx0, 1));
        mx0 = fmaxf(mx0, __shfl_xor_sync(~0u, mx0, 2));
        mx1 = fmaxf(mx1, __shfl_xor_sync(~0u, mx1, 1));
        mx1 = fmaxf(mx1, __shfl_xor_sync(~0u, mx1, 2));
        const float mLn0 = fmaxf(mL0, mx0 * L2E);
        const float mLn1 = fmaxf(mL1, mx1 * L2E);
        const float corr0 = exp2f(mL0 - mLn0);
        const float corr1 = exp2f(mL1 - mLn1);
        mL0 = mLn0; mL1 = mLn1;
        lacc[0] *= corr0; lacc[1] *= corr0; lacc[2] *= corr1; lacc[3] *= corr1;
#pragma unroll
        for (int nt = 0; nt < 8; nt++) {
            o[nt][0] *= corr0; o[nt][1] *= corr0; o[nt][2] *= corr1; o[nt][3] *= corr1;
        }
        uint32_t pf[4][4];
#pragma unroll
        for (int j = 0; j < 4; j++) {
            pf[j][0] = exp2_pack(fmaf(S[2*j][1],   L2E, -mL0), fmaf(S[2*j][0],   L2E, -mL0));
            pf[j][1] = exp2_pack(fmaf(S[2*j][3],   L2E, -mL1), fmaf(S[2*j][2],   L2E, -mL1));
            pf[j][2] = exp2_pack(fmaf(S[2*j+1][1], L2E, -mL0), fmaf(S[2*j+1][0], L2E, -mL0));
            pf[j][3] = exp2_pack(fmaf(S[2*j+1][3], L2E, -mL1), fmaf(S[2*j+1][2], L2E, -mL1));
        }
#pragma unroll
        for (int j = 0; j < 4; j++) mmaf16(lacc, pf[j], ones2);
#pragma unroll
        for (int j = 0; j < 4; j++) {
            const int krow = j*16 + (lane & 15);
#pragma unroll
            for (int pp = 0; pp < 4; pp++) {
                const int colb = (pp*16 + ((lane >> 4) << 3)) * 2;
                uint32_t vf[4];
                ldsm4t(vf, st + 8192 + swz((uint32_t)(krow*128 + colb)));
                mmaf16(o[2*pp],   pf[j], vf);
                mmaf16(o[2*pp+1], pf[j], vf + 2);
            }
        }
        __syncthreads();
    }

    const float inv0 = 1.0f / lacc[0];
    const float inv1 = 1.0f / lacc[2];
    const size_t r0 = (size_t)(b*SS + q0 + wid*16 + (lane >> 2));
    const size_t r1 = r0 + 8;
#pragma unroll
    for (int nt = 0; nt < 8; nt++) {
        const size_t col = hoff + 8*nt + 2*(lane & 3);
        *(__half2*)&c16[r0*DD + col] = __halves2half2(
            __float2half_rn(o[nt][0]*inv0), __float2half_rn(o[nt][1]*inv0));
        *(__half2*)&c16[r1*DD + col] = __halves2half2(
            __float2half_rn(o[nt][2]*inv1), __float2half_rn(o[nt][3]*inv1));
    }
}

// ---- warp-per-row LayerNorm: shuffle-only, no smem/bar ----
__global__ __launch_bounds__(256)
void ln_kernel(const float* __restrict__ Y, const float* __restrict__ R,
               const float* __restrict__ g, const float* __restrict__ bta,
               float* __restrict__ out, __half* __restrict__ h16) {
    const int row = blockIdx.x * 8 + (threadIdx.x >> 5);
    const int lane = threadIdx.x & 31;
    const float4* yp = (const float4*)(Y + (size_t)row * DD);
    const float4* rp = (const float4*)(R + (size_t)row * DD);

    float4 v[8];
    float s = 0.0f;
#pragma unroll
    for (int j = 0; j < 8; j++) {
        float4 a = yp[lane + 32 * j];
        const float4 b = rp[lane + 32 * j];
        a.x += b.x; a.y += b.y; a.z += b.z; a.w += b.w;
        v[j] = a;
        s += a.x + a.y + a.z + a.w;
    }
#pragma unroll
    for (int off = 16; off; off >>= 1) s += __shfl_xor_sync(~0u, s, off);
    const float mean = s * (1.0f / 1024.0f);

    float s2 = 0.0f;
#pragma unroll
    for (int j = 0; j < 8; j++) {
        const float dx = v[j].x - mean, dy = v[j].y - mean;
        const float dz = v[j].z - mean, dw = v[j].w - mean;
        s2 += dx*dx + dy*dy + dz*dz + dw*dw;
    }
#pragma unroll
    for (int off = 16; off; off >>= 1) s2 += __shfl_xor_sync(~0u, s2, off);
    const float rstd = rsqrtf(s2 * (1.0f / 1024.0f) + 1e-12f);

    float4* op = (float4*)(out + (size_t)row * DD);
#pragma unroll
    for (int j = 0; j < 8; j++) {
        const int idx = lane + 32 * j;
        const float4 gg = ((const float4*)g)[idx];
        const float4 bb = ((const float4*)bta)[idx];
        float4 o;
        o.x = (v[j].x - mean) * rstd * gg.x + bb.x;
        o.y = (v[j].y - mean) * rstd * gg.y + bb.y;
        o.z = (v[j].z - mean) * rstd * gg.z + bb.z;
        o.w = (v[j].w - mean) * rstd * gg.w + bb.w;
        op[idx] = o;
        if (h16) {
            ((__half2*)(h16 + (size_t)row * DD))[2*idx] =
                __halves2half2(__float2half_rn(o.x), __float2half_rn(o.y));
            ((__half2*)(h16 + (size_t)row * DD))[2*idx+1] =
                __halves2half2(__float2half_rn(o.z), __float2half_rn(o.w));
        }
    }
}

extern "C" void kernel_launch(void* const* d_in, const int* in_sizes, int n_in,
                              void* d_out, int out_size) {
    const float* x    = (const float*)d_in[0];
    const float* mask = (const float*)d_in[1];
    const float* Wq = (const float*)d_in[2];  const float* bq = (const float*)d_in[3];
    const float* Wk = (const float*)d_in[4];  const float* bk = (const float*)d_in[5];
    const float* Wv = (const float*)d_in[6];  const float* bv = (const float*)d_in[7];
    const float* Wo = (const float*)d_in[8];  const float* bo = (const float*)d_in[9];
    const float* ln1g = (const float*)d_in[10]; const float* ln1b = (const float*)d_in[11];
    const float* Wi = (const float*)d_in[12]; const float* bi = (const float*)d_in[13];
    const float* Wo2 = (const float*)d_in[14]; const float* bo2 = (const float*)d_in[15];
    const float* ln2g = (const float*)d_in[16]; const float* ln2b = (const float*)d_in[17];
    float* out = (float*)d_out;

    float *tmp, *res, *b3;
    __half *x16, *ln16, *c16, *f16, *q16, *k16, *v16, *wh;
    cudaGetSymbolAddress((void**)&tmp, g_tmp);
    cudaGetSymbolAddress((void**)&res, g_res);
    cudaGetSymbolAddress((void**)&b3, g_b3);
    cudaGetSymbolAddress((void**)&x16, g_x16);
    cudaGetSymbolAddress((void**)&ln16, g_ln16);
    cudaGetSymbolAddress((void**)&c16, g_c16);
    cudaGetSymbolAddress((void**)&f16, g_f16);
    cudaGetSymbolAddress((void**)&q16, g_q16);
    cudaGetSymbolAddress((void**)&k16, g_k16);
    cudaGetSymbolAddress((void**)&v16, g_v16);
    cudaGetSymbolAddress((void**)&wh, g_wh);

    cudaFuncSetAttribute(gemm_tc, cudaFuncAttributeMaxDynamicSharedMemorySize, GSMEM);
    cudaFuncSetAttribute(attn_mma, cudaFuncAttributeMaxDynamicSharedMemorySize, AT_SMEM);

    megaprep_kernel<<<14339, 256>>>(Wq, Wk, Wv, Wo, Wi, Wo2, x, bq, bk, bv, wh, x16, b3);

    gemm_tc<<<dim3(QKVW/128, MM/128), 256, GSMEM>>>(x16, wh + W_QKV, b3,
        0, 0, q16, k16, v16, QKVW, DD, 0, 2);
    attn_mma<<<dim3(SS/128, BB*16), 256, AT_SMEM>>>(q16, k16, v16, mask, c16);
    gemm_tc<<<dim3(DD/128, MM/128), 256, GSMEM>>>(c16, wh + W_O, bo,
        tmp, 0, 0, 0, 0, DD, DD, 0, 0);
    ln_kernel<<<MM/8, 256>>>(tmp, x, ln1g, ln1b, res, ln16);
    gemm_tc<<<dim3(DFFN/128, MM/128), 256, GSMEM>>>(ln16, wh + W_I, bi,
        0, f16, 0, 0, 0, DFFN, DD, 1, 1);
    gemm_tc<<<dim3(DD/128, MM/128), 256, GSMEM>>>(f16, wh + W_O2, bo2,
        tmp, 0, 0, 0, 0, DD, DFFN, 0, 0);
    ln_kernel<<<MM/8, 256>>>(tmp, res, ln2g, ln2b, out, 0);
}

// round 13
// speedup vs baseline: 3.8272x; 1.0243x over previous
#include <cuda_runtime.h>
#include <cuda_bf16.h>
#include <cuda_fp16.h>
#include <math.h>
#include <stdint.h>

#define BB 4
#define SS 2048
#define DD 1024
#define DFFN 4096
#define MM (BB*SS)
#define QKVW 3072
#define L2E 1.44269504088896f

__device__ float g_tmp[(size_t)MM * DD];
__device__ float g_res[(size_t)MM * DD];
__device__ __half g_x16[(size_t)MM * DD];
__device__ __half g_ln16[(size_t)MM * DD];
__device__ __half g_c16[(size_t)MM * DD];
__device__ __half g_f16[(size_t)MM * DFFN];
__device__ __half g_q16[(size_t)MM * DD];
__device__ __half g_k16[(size_t)MM * DD];
__device__ __half g_v16[(size_t)MM * DD];
#define W_QKV 0u
#define W_O   (3u*1024*1024)
#define W_I   (4u*1024*1024)
#define W_O2  (8u*1024*1024)
__device__ __half g_wh[12u*1024*1024];
__device__ float g_b3[QKVW];

__device__ __forceinline__ float gelu_f(float x) {
    return 0.5f * x * (1.0f + erff(x * 0.70710678118654752f));
}
__device__ __forceinline__ uint32_t s2u(const void* p) {
    uint32_t a;
    asm("{ .reg .u64 t; cvta.to.shared.u64 t, %1; cvt.u32.u64 %0, t; }" : "=r"(a) : "l"(p));
    return a;
}
__device__ __forceinline__ uint32_t swz(uint32_t off) {
    return off ^ (((off >> 7) & 7u) << 4);
}
__device__ __forceinline__ void cpa(uint32_t dst, const void* src) {
    asm volatile("cp.async.cg.shared.global [%0], [%1], 16;" :: "r"(dst), "l"(src));
}
__device__ __forceinline__ void ldsm4(uint32_t* r, uint32_t addr) {
    asm volatile("ldmatrix.sync.aligned.m8n8.x4.shared.b16 {%0,%1,%2,%3}, [%4];"
        : "=r"(r[0]), "=r"(r[1]), "=r"(r[2]), "=r"(r[3]) : "r"(addr));
}
__device__ __forceinline__ void ldsm4t(uint32_t* r, uint32_t addr) {
    asm volatile("ldmatrix.sync.aligned.m8n8.x4.trans.shared.b16 {%0,%1,%2,%3}, [%4];"
        : "=r"(r[0]), "=r"(r[1]), "=r"(r[2]), "=r"(r[3]) : "r"(addr));
}
__device__ __forceinline__ void mmaf16(float* d, const uint32_t* a, const uint32_t* b) {
    asm volatile("mma.sync.aligned.m16n8k16.row.col.f32.f16.f16.f32 "
        "{%0,%1,%2,%3}, {%4,%5,%6,%7}, {%8,%9}, {%0,%1,%2,%3};"
        : "+f"(d[0]), "+f"(d[1]), "+f"(d[2]), "+f"(d[3])
        : "r"(a[0]), "r"(a[1]), "r"(a[2]), "r"(a[3]), "r"(b[0]), "r"(b[1]));
}
// MUFU f16x2 exp2: pack (even->lo, odd->hi) then 2^x on both halves
__device__ __forceinline__ uint32_t exp2_pack(float odd, float even) {
    uint32_t p, r;
    asm("cvt.rn.f16x2.f32 %0, %1, %2;" : "=r"(p) : "f"(odd), "f"(even));
    asm("ex2.approx.f16x2 %0, %1;" : "=r"(r) : "r"(p));
    return r;
}

// ---- megaprep: 6 weight transposes + x->fp16 + bias pack, ONE launch ----
__device__ __forceinline__ void wconv_tile(const float* __restrict__ W, int N, int K,
                                           __half* __restrict__ hi, int bx, int by,
                                           int tx, int ty) {
    __shared__ float t[32][33];
    const int n0 = bx * 32, k0 = by * 32;
    for (int j = ty; j < 32; j += 8) t[j][tx] = W[(size_t)(k0 + j) * N + n0 + tx];
    __syncthreads();
    for (int j = ty; j < 32; j += 8)
        hi[(size_t)(n0 + j) * K + k0 + tx] = __float2half_rn(t[tx][j]);
}

__global__ __launch_bounds__(256)
void megaprep_kernel(const float* __restrict__ Wq, const float* __restrict__ Wk,
                     const float* __restrict__ Wv, const float* __restrict__ Wo,
                     const float* __restrict__ Wi, const float* __restrict__ Wo2,
                     const float* __restrict__ x,
                     const float* __restrict__ bq, const float* __restrict__ bk,
                     const float* __restrict__ bv,
                     __half* __restrict__ wh, __half* __restrict__ x16,
                     float* __restrict__ b3) {
    const int b = blockIdx.x;
    const int tx = threadIdx.x & 31, ty = threadIdx.x >> 5;
    if (b < 4096) {
        const int which = b >> 10, idx = b & 1023;
        const int bx = idx & 31, by = idx >> 5;
        const float* W = (which == 0) ? Wq : (which == 1) ? Wk : (which == 2) ? Wv : Wo;
        __half* dst = wh + ((which < 3) ? (W_QKV + (uint32_t)which * 1048576u) : W_O);
        wconv_tile(W, DD, DD, dst, bx, by, tx, ty);
    } else if (b < 8192) {
        const int idx = b - 4096;
        wconv_tile(Wi, DFFN, DD, wh + W_I, idx & 127, idx >> 7, tx, ty);
    } else if (b < 12288) {
        const int idx = b - 8192;
        wconv_tile(Wo2, DD, DFFN, wh + W_O2, idx & 31, idx >> 5, tx, ty);
    } else if (b < 14336) {
        const int tid = threadIdx.x;
        for (int i = (b - 12288) * 256 + tid; i < MM * DD / 4; i += 2048 * 256) {
            const float4 v = ((const float4*)x)[i];
            ((__half2*)x16)[2*i+0] = __halves2half2(__float2half_rn(v.x), __float2half_rn(v.y));
            ((__half2*)x16)[2*i+1] = __halves2half2(__float2half_rn(v.z), __float2half_rn(v.w));
        }
    } else {
        const int which = b - 14336;
        const float* s = (which == 0) ? bq : (which == 1) ? bk : bv;
        for (int i = threadIdx.x; i < 1024; i += 256)
            b3[which * 1024 + i] = s[i];
    }
}

// ---- fp16 GEMM: C[M,N] = A16[M,K] @ B16[N,K]^T + bias ----
// CTA 128x128, BK=64, 3-stage cp.async, occ 2, one sync/iter, XOR-hoisted addrs.
#define STG_B 32768
#define T_A  0
#define T_B  16384
#define GSMEM (3*STG_B)

__device__ __forceinline__ void load_stage(uint32_t sbase,
    const __half* __restrict__ A, const __half* __restrict__ B,
    int K, int m0, int n0, int kb) {
    for (int i = threadIdx.x; i < 1024; i += 256) {
        const int row = i >> 3, cc = (i & 7) << 3;
        const uint32_t so = swz((uint32_t)(row * 128 + cc * 2));
        cpa(sbase + T_A + so, A + (size_t)(m0 + row) * K + kb + cc);
        cpa(sbase + T_B + so, B + (size_t)(n0 + row) * K + kb + cc);
    }
}

// mode 0: Cf fp32. mode 1: C16 fp16 (+act). mode 2: q/k/v fp16 out.
__global__ __launch_bounds__(256, 2)
void gemm_tc(const __half* __restrict__ A, const __half* __restrict__ B,
             const float* __restrict__ bias, float* __restrict__ Cf,
             __half* __restrict__ C16,
             __half* __restrict__ Q16, __half* __restrict__ K16, __half* __restrict__ V16,
             int N, int K, int act, int mode) {
    extern __shared__ char smv[];
    const uint32_t sb = s2u(smv);
    const int tid = threadIdx.x, lane = tid & 31, wid = tid >> 5;
    const int wm = wid & 3, wn = wid >> 2;
    const int m0 = blockIdx.y << 7, n0 = blockIdx.x << 7;
    const int nc = K >> 6;

    float acc[2][8][4];
#pragma unroll
    for (int i = 0; i < 2; i++)
#pragma unroll
        for (int j = 0; j < 8; j++)
#pragma unroll
            for (int q = 0; q < 4; q++) acc[i][j][q] = 0.0f;

    load_stage(sb, A, B, K, m0, n0, 0);
    asm volatile("cp.async.commit_group;" ::: "memory");
    load_stage(sb + STG_B, A, B, K, m0, n0, 64);
    asm volatile("cp.async.commit_group;" ::: "memory");

    const int a_r = (lane & 15);
    const int a_c = (lane >> 4) << 3;
    const int b_r = (lane & 7) + ((lane >> 4) << 3);
    const int b_c = ((lane >> 3) & 1) << 3;

    // ks=0 base addresses; addr(ks) = base ^ (ks<<5)
    uint32_t aoff[2], boff[4];
#pragma unroll
    for (int mt = 0; mt < 2; mt++)
        aoff[mt] = swz((uint32_t)((wm*32 + mt*16 + a_r)*128 + a_c*2));
#pragma unroll
    for (int p = 0; p < 4; p++)
        boff[p] = swz((uint32_t)((wn*64 + p*16 + b_r)*128 + b_c*2));

    for (int c = 0; c < nc; c++) {
        asm volatile("cp.async.wait_group 1;" ::: "memory");
        __syncthreads();
        if (c + 2 < nc)
            load_stage(sb + (uint32_t)((c + 2) % 3) * STG_B, A, B, K, m0, n0, (c + 2) << 6);
        asm volatile("cp.async.commit_group;" ::: "memory");

        const uint32_t stA = sb + (uint32_t)(c % 3) * STG_B + T_A;
        const uint32_t stB = sb + (uint32_t)(c % 3) * STG_B + T_B;
#pragma unroll
        for (int ks = 0; ks < 4; ks++) {
            const uint32_t kx = (uint32_t)ks << 5;
            uint32_t af[2][4], bf[8][2];
#pragma unroll
            for (int mt = 0; mt < 2; mt++)
                ldsm4(af[mt], stA + (aoff[mt] ^ kx));
#pragma unroll
            for (int p = 0; p < 4; p++) {
                uint32_t t4[4];
                ldsm4(t4, stB + (boff[p] ^ kx));
                bf[2*p][0]=t4[0]; bf[2*p][1]=t4[1]; bf[2*p+1][0]=t4[2]; bf[2*p+1][1]=t4[3];
            }
#pragma unroll
            for (int mt = 0; mt < 2; mt++)
#pragma unroll
                for (int nt = 0; nt < 8; nt++)
                    mmaf16(acc[mt][nt], af[mt], bf[nt]);
        }
    }

    const int rbase = m0 + wm * 32 + (lane >> 2);
    const int cbase = n0 + wn * 64 + ((lane & 3) << 1);
    const int region = n0 >> 10;
#pragma unroll
    for (int mt = 0; mt < 2; mt++) {
#pragma unroll
        for (int nt = 0; nt < 8; nt++) {
            const int col = cbase + nt * 8;
            const float2 bv = *(const float2*)&bias[col];
            float v0 = acc[mt][nt][0] + bv.x, v1 = acc[mt][nt][1] + bv.y;
            float v2 = acc[mt][nt][2] + bv.x, v3 = acc[mt][nt][3] + bv.y;
            if (act) { v0 = gelu_f(v0); v1 = gelu_f(v1); v2 = gelu_f(v2); v3 = gelu_f(v3); }
            const size_t r0 = (size_t)(rbase + mt * 16);
            const size_t r1 = r0 + 8;
            if (mode == 0) {
                *(float2*)&Cf[r0 * N + col] = make_float2(v0, v1);
                *(float2*)&Cf[r1 * N + col] = make_float2(v2, v3);
            } else if (mode == 1) {
                *(__half2*)&C16[r0 * N + col] = __halves2half2(__float2half_rn(v0), __float2half_rn(v1));
                *(__half2*)&C16[r1 * N + col] = __halves2half2(__float2half_rn(v2), __float2half_rn(v3));
            } else {
                const size_t cl_ = (size_t)(col - (region << 10));
                __half* D = (region == 0) ? Q16 : (region == 1) ? K16 : V16;
                *(__half2*)&D[r0 * DD + cl_] = __halves2half2(__float2half_rn(v0), __float2half_rn(v1));
                *(__half2*)&D[r1 * DD + cl_] = __halves2half2(__float2half_rn(v2), __float2half_rn(v3));
            }
        }
    }
}

// ---- fp16 flash attention: 128 q-rows/CTA, MUFU f16x2 exp, occ 2, 1 sync/iter ----
#define AT_Q 0
#define AT_ST 16384
#define AT_SSZ 16640
#define AT_SMEM (16384 + 3*16640)

__global__ __launch_bounds__(256, 2)
void attn_mma(const __half* __restrict__ q16, const __half* __restrict__ k16,
              const __half* __restrict__ v16, const float* __restrict__ mask,
              __half* __restrict__ c16) {
    extern __shared__ char smv[];
    const uint32_t sb = s2u(smv);
    const int tid = threadIdx.x, lane = tid & 31, wid = tid >> 5;
    const int b = blockIdx.y >> 4, h = blockIdx.y & 15;
    const int q0 = blockIdx.x << 7;
    const size_t hoff = (size_t)h * 64;

    for (int i = tid; i < 1024; i += 256) {
        const int row = i >> 3, cc = i & 7;
        cpa(sb + AT_Q + swz((uint32_t)(row*128 + cc*16)),
            q16 + (size_t)(b*SS + q0 + row)*DD + hoff + cc*8);
    }
    for (int sidx = 0; sidx < 2; sidx++) {
        const int kt = sidx << 6;
        const uint32_t base = sb + AT_ST + (uint32_t)sidx * AT_SSZ;
        for (int i = tid; i < 1024; i += 256) {
            const int t = i >> 9, idx = i & 511, row = idx >> 3, cc = idx & 7;
            const __half* src = (t ? v16 : k16) + (size_t)(b*SS + kt + row)*DD + hoff + cc*8;
            cpa(base + t*8192 + swz((uint32_t)(row*128 + cc*16)), src);
        }
        if (tid < 16) cpa(base + 16384 + tid*16, mask + (size_t)b*SS + kt + tid*4);
        asm volatile("cp.async.commit_group;" ::: "memory");
    }

    uint32_t qf[4][4];
    float o[8][4], lacc[4];
    float mL0 = -1e30f, mL1 = -1e30f;
#pragma unroll
    for (int nt = 0; nt < 8; nt++) { o[nt][0]=o[nt][1]=o[nt][2]=o[nt][3]=0.f; }
    lacc[0]=lacc[1]=lacc[2]=lacc[3]=0.f;
    const uint32_t ones2[2] = {0x3C003C00u, 0x3C003C00u};

    // hoisted base addresses: addr = base ^ (ks<<5) / (pp<<5)
    uint32_t kboff[4];
#pragma unroll
    for (int p = 0; p < 4; p++)
        kboff[p] = swz((uint32_t)((p*16 + (lane & 7) + ((lane >> 4) << 3))*128
                                  + ((((lane >> 3) & 1) << 3)) * 2));
    const uint32_t vboff = swz((uint32_t)((lane & 15)*128 + (((lane >> 4) << 3)) * 2));

    for (int c = 0; c < SS/64; c++) {
        asm volatile("cp.async.wait_group 1;" ::: "memory");
        __syncthreads();
        if (c + 2 < SS/64) {
            const int kt = (c + 2) << 6;
            const uint32_t base = sb + AT_ST + (uint32_t)((c+2) % 3) * AT_SSZ;
            for (int i = tid; i < 1024; i += 256) {
                const int t = i >> 9, idx = i & 511, row = idx >> 3, cc = idx & 7;
                const __half* src = (t ? v16 : k16) + (size_t)(b*SS + kt + row)*DD + hoff + cc*8;
                cpa(base + t*8192 + swz((uint32_t)(row*128 + cc*16)), src);
            }
            if (tid < 16) cpa(base + 16384 + tid*16, mask + (size_t)b*SS + kt + tid*4);
        }
        asm volatile("cp.async.commit_group;" ::: "memory");

        if (c == 0) {
#pragma unroll
            for (int ks = 0; ks < 4; ks++) {
                const int row = wid*16 + (lane & 15);
                const int colb = (ks*16 + ((lane >> 4) << 3)) * 2;
                ldsm4(qf[ks], sb + AT_Q + swz((uint32_t)(row*128 + colb)));
            }
        }

        const uint32_t soff = AT_ST + (uint32_t)(c % 3) * AT_SSZ;
        const uint32_t st = sb + soff;
        float S[8][4];
#pragma unroll
        for (int nt = 0; nt < 8; nt++) { S[nt][0]=S[nt][1]=S[nt][2]=S[nt][3]=0.f; }
#pragma unroll
        for (int ks = 0; ks < 4; ks++) {
            const uint32_t kx = (uint32_t)ks << 5;
            uint32_t kb[8][2];
#pragma unroll
            for (int p = 0; p < 4; p++) {
                uint32_t t4[4];
                ldsm4(t4, st + (kboff[p] ^ kx));
                kb[2*p][0]=t4[0]; kb[2*p][1]=t4[1]; kb[2*p+1][0]=t4[2]; kb[2*p+1][1]=t4[3];
            }
#pragma unroll
            for (int nt = 0; nt < 8; nt++)
                mmaf16(S[nt], qf[ks], kb[nt]);
        }
#pragma unroll
        for (int nt = 0; nt < 8; nt++) {
            const float2 mv = *(const float2*)(smv + soff + 16384 + (8*nt + 2*(lane&3))*4);
            S[nt][0] = fmaf(S[nt][0], 0.125f, mv.x);
            S[nt][1] = fmaf(S[nt][1], 0.125f, mv.y);
            S[nt][2] = fmaf(S[nt][2], 0.125f, mv.x);
            S[nt][3] = fmaf(S[nt][3], 0.125f, mv.y);
        }
        float mx0 = -1e30f, mx1 = -1e30f;
#pragma unroll
        for (int nt = 0; nt < 8; nt++) {
            mx0 = fmaxf(mx0, fmaxf(S[nt][0], S[nt][1]));
            mx1 = fmaxf(mx1, fmaxf(S[nt][2], S[nt][3]));
        }
        mx0 = fmaxf(mx0, __shfl_xor_sync(~0u, mx0, 1));
        mx0 = fmaxf(mx0, __shfl_xor_sync(~0u, mx0, 2));
        mx1 = fmaxf(mx1, __shfl_xor_sync(~0u, mx1, 1));
        mx1 = fmaxf(mx1, __shfl_xor_sync(~0u, mx1, 2));
        const float mLn0 = fmaxf(mL0, mx0 * L2E);
        const float mLn1 = fmaxf(mL1, mx1 * L2E);
        const float corr0 = exp2f(mL0 - mLn0);
        const float corr1 = exp2f(mL1 - mLn1);
        mL0 = mLn0; mL1 = mLn1;
        lacc[0] *= corr0; lacc[1] *= corr0; lacc[2] *= corr1; lacc[3] *= corr1;
#pragma unroll
        for (int nt = 0; nt < 8; nt++) {
            o[nt][0] *= corr0; o[nt][1] *= corr0; o[nt][2] *= corr1; o[nt][3] *= corr1;
        }
        uint32_t pf[4][4];
#pragma unroll
        for (int j = 0; j < 4; j++) {
            pf[j][0] = exp2_pack(fmaf(S[2*j][1],   L2E, -mL0), fmaf(S[2*j][0],   L2E, -mL0));
            pf[j][1] = exp2_pack(fmaf(S[2*j][3],   L2E, -mL1), fmaf(S[2*j][2],   L2E, -mL1));
            pf[j][2] = exp2_pack(fmaf(S[2*j+1][1], L2E, -mL0), fmaf(S[2*j+1][0], L2E, -mL0));
            pf[j][3] = exp2_pack(fmaf(S[2*j+1][3], L2E, -mL1), fmaf(S[2*j+1][2], L2E, -mL1));
        }
#pragma unroll
        for (int j = 0; j < 4; j++) mmaf16(lacc, pf[j], ones2);
#pragma unroll
        for (int j = 0; j < 4; j++) {
            const uint32_t vbase = st + 8192 + (uint32_t)(j * 2048);
#pragma unroll
            for (int pp = 0; pp < 4; pp++) {
                uint32_t vf[4];
                ldsm4t(vf, vbase + (vboff ^ ((uint32_t)pp << 5)));
                mmaf16(o[2*pp],   pf[j], vf);
                mmaf16(o[2*pp+1], pf[j], vf + 2);
            }
        }
    }

    const float inv0 = 1.0f / lacc[0];
    const float inv1 = 1.0f / lacc[2];
    const size_t r0 = (size_t)(b*SS + q0 + wid*16 + (lane >> 2));
    const size_t r1 = r0 + 8;
#pragma unroll
    for (int nt = 0; nt < 8; nt++) {
        const size_t col = hoff + 8*nt + 2*(lane & 3);
        *(__half2*)&c16[r0*DD + col] = __halves2half2(
            __float2half_rn(o[nt][0]*inv0), __float2half_rn(o[nt][1]*inv0));
        *(__half2*)&c16[r1*DD + col] = __halves2half2(
            __float2half_rn(o[nt][2]*inv1), __float2half_rn(o[nt][3]*inv1));
    }
}

// ---- warp-per-row LayerNorm: shuffle-only, no smem/bar ----
__global__ __launch_bounds__(256)
void ln_kernel(const float* __restrict__ Y, const float* __restrict__ R,
               const float* __restrict__ g, const float* __restrict__ bta,
               float* __restrict__ out, __half* __restrict__ h16) {
    const int row = blockIdx.x * 8 + (threadIdx.x >> 5);
    const int lane = threadIdx.x & 31;
    const float4* yp = (const float4*)(Y + (size_t)row * DD);
    const float4* rp = (const float4*)(R + (size_t)row * DD);

    float4 v[8];
    float s = 0.0f;
#pragma unroll
    for (int j = 0; j < 8; j++) {
        float4 a = yp[lane + 32 * j];
        const float4 b = rp[lane + 32 * j];
        a.x += b.x; a.y += b.y; a.z += b.z; a.w += b.w;
        v[j] = a;
        s += a.x + a.y + a.z + a.w;
    }
#pragma unroll
    for (int off = 16; off; off >>= 1) s += __shfl_xor_sync(~0u, s, off);
    const float mean = s * (1.0f / 1024.0f);

    float s2 = 0.0f;
#pragma unroll
    for (int j = 0; j < 8; j++) {
        const float dx = v[j].x - mean, dy = v[j].y - mean;
        const float dz = v[j].z - mean, dw = v[j].w - mean;
        s2 += dx*dx + dy*dy + dz*dz + dw*dw;
    }
#pragma unroll
    for (int off = 16; off; off >>= 1) s2 += __shfl_xor_sync(~0u, s2, off);
    const float rstd = rsqrtf(s2 * (1.0f / 1024.0f) + 1e-12f);

    float4* op = (float4*)(out + (size_t)row * DD);
#pragma unroll
    for (int j = 0; j < 8; j++) {
        const int idx = lane + 32 * j;
        const float4 gg = ((const float4*)g)[idx];
        const float4 bb = ((const float4*)bta)[idx];
        float4 o;
        o.x = (v[j].x - mean) * rstd * gg.x + bb.x;
        o.y = (v[j].y - mean) * rstd * gg.y + bb.y;
        o.z = (v[j].z - mean) * rstd * gg.z + bb.z;
        o.w = (v[j].w - mean) * rstd * gg.w + bb.w;
        op[idx] = o;
        if (h16) {
            ((__half2*)(h16 + (size_t)row * DD))[2*idx] =
                __halves2half2(__float2half_rn(o.x), __float2half_rn(o.y));
            ((__half2*)(h16 + (size_t)row * DD))[2*idx+1] =
                __halves2half2(__float2half_rn(o.z), __float2half_rn(o.w));
        }
    }
}

extern "C" void kernel_launch(void* const* d_in, const int* in_sizes, int n_in,
                              void* d_out, int out_size) {
    const float* x    = (const float*)d_in[0];
    const float* mask = (const float*)d_in[1];
    const float* Wq = (const float*)d_in[2];  const float* bq = (const float*)d_in[3];
    const float* Wk = (const float*)d_in[4];  const float* bk = (const float*)d_in[5];
    const float* Wv = (const float*)d_in[6];  const float* bv = (const float*)d_in[7];
    const float* Wo = (const float*)d_in[8];  const float* bo = (const float*)d_in[9];
    const float* ln1g = (const float*)d_in[10]; const float* ln1b = (const float*)d_in[11];
    const float* Wi = (const float*)d_in[12]; const float* bi = (const float*)d_in[13];
    const float* Wo2 = (const float*)d_in[14]; const float* bo2 = (const float*)d_in[15];
    const float* ln2g = (const float*)d_in[16]; const float* ln2b = (const float*)d_in[17];
    float* out = (float*)d_out;

    float *tmp, *res, *b3;
    __half *x16, *ln16, *c16, *f16, *q16, *k16, *v16, *wh;
    cudaGetSymbolAddress((void**)&tmp, g_tmp);
    cudaGetSymbolAddress((void**)&res, g_res);
    cudaGetSymbolAddress((void**)&b3, g_b3);
    cudaGetSymbolAddress((void**)&x16, g_x16);
    cudaGetSymbolAddress((void**)&ln16, g_ln16);
    cudaGetSymbolAddress((void**)&c16, g_c16);
    cudaGetSymbolAddress((void**)&f16, g_f16);
    cudaGetSymbolAddress((void**)&q16, g_q16);
    cudaGetSymbolAddress((void**)&k16, g_k16);
    cudaGetSymbolAddress((void**)&v16, g_v16);
    cudaGetSymbolAddress((void**)&wh, g_wh);

    cudaFuncSetAttribute(gemm_tc, cudaFuncAttributeMaxDynamicSharedMemorySize, GSMEM);
    cudaFuncSetAttribute(attn_mma, cudaFuncAttributeMaxDynamicSharedMemorySize, AT_SMEM);

    megaprep_kernel<<<14339, 256>>>(Wq, Wk, Wv, Wo, Wi, Wo2, x, bq, bk, bv, wh, x16, b3);

    gemm_tc<<<dim3(QKVW/128, MM/128), 256, GSMEM>>>(x16, wh + W_QKV, b3,
        0, 0, q16, k16, v16, QKVW, DD, 0, 2);
    attn_mma<<<dim3(SS/128, BB*16), 256, AT_SMEM>>>(q16, k16, v16, mask, c16);
    gemm_tc<<<dim3(DD/128, MM/128), 256, GSMEM>>>(c16, wh + W_O, bo,
        tmp, 0, 0, 0, 0, DD, DD, 0, 0);
    ln_kernel<<<MM/8, 256>>>(tmp, x, ln1g, ln1b, res, ln16);
    gemm_tc<<<dim3(DFFN/128, MM/128), 256, GSMEM>>>(ln16, wh + W_I, bi,
        0, f16, 0, 0, 0, DFFN, DD, 1, 1);
    gemm_tc<<<dim3(DD/128, MM/128), 256, GSMEM>>>(f16, wh + W_O2, bo2,
        tmp, 0, 0, 0, 0, DD, DFFN, 0, 0);
    ln_kernel<<<MM/8, 256>>>(tmp, res, ln2g, ln2b, out, 0);
}